// round 4
// baseline (speedup 1.0000x reference)
#include <cuda_runtime.h>
#include <math.h>

#define HID   512
#define BATCH 64
#define NSEQ  128
#define TENC  256
#define TDEC  48
#define G3    1536   // 3*H
#define CIN   1024   // 2*H

#define WST 516      // weight row stride (floats); 516%32=4 -> conflict-free row banks
#define HST 516      // enc h row stride
#define DST 132      // dec h chunk row stride; 132%32=4

// ---------------- scratch ----------------
__device__ float g_GI0[(size_t)TENC * NSEQ * G3];
__device__ float g_GI1[(size_t)TDEC * NSEQ * G3];
__device__ float g_WeT[(size_t)CIN * G3];
__device__ float g_WdT[(size_t)HID * G3];
__device__ float g_hA[NSEQ * HID];
__device__ float g_hB[NSEQ * HID];
__device__ unsigned g_flags[128];

// ---------------- helpers ----------------
__device__ __forceinline__ void fma2(unsigned long long& acc, double a, double b) {
    asm("fma.rn.f32x2 %0, %1, %2, %0;"
        : "+l"(acc)
        : "l"(__double_as_longlong(a)), "l"(__double_as_longlong(b)));
}
__device__ __forceinline__ float pairsum(unsigned long long v) {
    return __uint_as_float((unsigned)v) + __uint_as_float((unsigned)(v >> 32));
}
__device__ __forceinline__ float sigmoidf_(float x) { return 1.f / (1.f + expf(-x)); }

__device__ __forceinline__ unsigned ld_acq(const unsigned* p) {
    unsigned v;
    asm volatile("ld.acquire.gpu.global.u32 %0, [%1];" : "=r"(v) : "l"(p) : "memory");
    return v;
}
__device__ __forceinline__ void st_rel(unsigned* p, unsigned v) {
    asm volatile("st.release.gpu.global.u32 [%0], %1;" :: "l"(p), "r"(v) : "memory");
}

// epoch barrier over CTA set [base, base+size)
__device__ __forceinline__ void step_barrier(int base, int size, unsigned epoch) {
    __threadfence();
    __syncthreads();
    if (threadIdx.x == 0) st_rel(&g_flags[blockIdx.x], epoch);
    if (threadIdx.x < (unsigned)size) {
        while (ld_acq(&g_flags[base + threadIdx.x]) < epoch) { }
    }
    __syncthreads();
}

// ---------------- weight transpose ----------------
__global__ void transpose_w(const float* __restrict__ src, int which) {
    __shared__ float tile[32][33];
    float* dst = which ? g_WdT : g_WeT;
    int cOff   = which ? 512 : 0;
    int c0 = blockIdx.x * 32, j0 = blockIdx.y * 32;
    int x = threadIdx.x, y = threadIdx.y;
    #pragma unroll
    for (int yy = y; yy < 32; yy += 8)
        tile[yy][x] = src[(size_t)(j0 + yy) * CIN + cOff + c0 + x];
    __syncthreads();
    #pragma unroll
    for (int yy = y; yy < 32; yy += 8)
        dst[(size_t)(c0 + yy) * G3 + j0 + x] = tile[x][yy];
}

__global__ void zero_h() {
    int i = blockIdx.x * 256 + threadIdx.x;
    if (i < NSEQ * HID) g_hA[i] = 0.f;
    if (i < 128) g_flags[i] = 0u;
}

// ---------------- encoder GI GEMM ----------------
__global__ void __launch_bounds__(256) gemm_enc(const float* __restrict__ X0,
                                                const float* __restrict__ bih) {
    __shared__ float As[16][128];
    __shared__ float Bs[16][128];
    int m0 = blockIdx.y * 128, j0 = blockIdx.x * 128;
    int tid = threadIdx.x;
    int tx = tid & 15, ty = tid >> 4;
    int bb = m0 >> 9;
    int t0base = m0 & 511;
    float acc[8][8];
    #pragma unroll
    for (int u = 0; u < 8; u++)
        #pragma unroll
        for (int v = 0; v < 8; v++) acc[u][v] = 0.f;

    for (int c0 = 0; c0 < CIN; c0 += 16) {
        #pragma unroll
        for (int l = 0; l < 2; l++) {
            int idx4 = tid + 256 * l;
            int mm4 = idx4 & 31, cc = idx4 >> 5;
            float4 va = *(const float4*)(X0 + ((size_t)(bb * CIN + c0 + cc)) * 512 + t0base + mm4 * 4);
            *(float4*)(&As[cc][mm4 * 4]) = va;
            float4 vb = *(const float4*)(g_WeT + (size_t)(c0 + cc) * G3 + j0 + mm4 * 4);
            *(float4*)(&Bs[cc][mm4 * 4]) = vb;
        }
        __syncthreads();
        #pragma unroll
        for (int k = 0; k < 16; k++) {
            float a[8], bv[8];
            #pragma unroll
            for (int u = 0; u < 8; u++) a[u] = As[k][ty * 8 + u];
            #pragma unroll
            for (int v = 0; v < 8; v++) bv[v] = Bs[k][tx * 8 + v];
            #pragma unroll
            for (int u = 0; u < 8; u++)
                #pragma unroll
                for (int v = 0; v < 8; v++) acc[u][v] += a[u] * bv[v];
        }
        __syncthreads();
    }
    float bias[8];
    #pragma unroll
    for (int v = 0; v < 8; v++) bias[v] = bih[j0 + tx * 8 + v];
    #pragma unroll
    for (int u = 0; u < 8; u++) {
        int m = m0 + ty * 8 + u;
        int t0 = m & 511;
        int n = ((t0 & 1) << 6) | (m >> 9);
        size_t base = ((size_t)((t0 >> 1) * NSEQ + n)) * G3 + j0 + tx * 8;
        float4 o1, o2;
        o1.x = acc[u][0] + bias[0]; o1.y = acc[u][1] + bias[1];
        o1.z = acc[u][2] + bias[2]; o1.w = acc[u][3] + bias[3];
        o2.x = acc[u][4] + bias[4]; o2.y = acc[u][5] + bias[5];
        o2.z = acc[u][6] + bias[6]; o2.w = acc[u][7] + bias[7];
        *(float4*)(g_GI0 + base)     = o1;
        *(float4*)(g_GI0 + base + 4) = o2;
    }
}

// ---------------- decoder GI GEMM ----------------
__global__ void __launch_bounds__(256) gemm_dec(const float* __restrict__ X1,
                                                const float* __restrict__ bih) {
    __shared__ float As[16][128];
    __shared__ float Bs[16][128];
    int m0 = blockIdx.y * 128, j0 = blockIdx.x * 128;
    int tid = threadIdx.x;
    int tx = tid & 15, ty = tid >> 4;
    float acc[8][8];
    #pragma unroll
    for (int u = 0; u < 8; u++)
        #pragma unroll
        for (int v = 0; v < 8; v++) acc[u][v] = 0.f;

    for (int c0 = 0; c0 < HID; c0 += 16) {
        #pragma unroll
        for (int l = 0; l < 8; l++) {
            int idx = tid + 256 * l;
            int r = idx & 127, cc = idx >> 7;
            int m = m0 + r;
            int b = m / 96;
            int t0 = m - b * 96;
            As[cc][r] = X1[((size_t)(b * HID + c0 + cc)) * 96 + t0];
        }
        #pragma unroll
        for (int l = 0; l < 2; l++) {
            int idx4 = tid + 256 * l;
            int jj4 = idx4 & 31, cc = idx4 >> 5;
            float4 vb = *(const float4*)(g_WdT + (size_t)(c0 + cc) * G3 + j0 + jj4 * 4);
            *(float4*)(&Bs[cc][jj4 * 4]) = vb;
        }
        __syncthreads();
        #pragma unroll
        for (int k = 0; k < 16; k++) {
            float a[8], bv[8];
            #pragma unroll
            for (int u = 0; u < 8; u++) a[u] = As[k][ty * 8 + u];
            #pragma unroll
            for (int v = 0; v < 8; v++) bv[v] = Bs[k][tx * 8 + v];
            #pragma unroll
            for (int u = 0; u < 8; u++)
                #pragma unroll
                for (int v = 0; v < 8; v++) acc[u][v] += a[u] * bv[v];
        }
        __syncthreads();
    }
    float bias[8];
    #pragma unroll
    for (int v = 0; v < 8; v++) bias[v] = bih[j0 + tx * 8 + v];
    #pragma unroll
    for (int u = 0; u < 8; u++) {
        int m = m0 + ty * 8 + u;
        int b = m / 96;
        int t0 = m - b * 96;
        int n = ((t0 & 1) << 6) | b;
        size_t base = ((size_t)((t0 >> 1) * NSEQ + n)) * G3 + j0 + tx * 8;
        float4 o1, o2;
        o1.x = acc[u][0] + bias[0]; o1.y = acc[u][1] + bias[1];
        o1.z = acc[u][2] + bias[2]; o1.w = acc[u][3] + bias[3];
        o2.x = acc[u][4] + bias[4]; o2.y = acc[u][5] + bias[5];
        o2.z = acc[u][6] + bias[6]; o2.w = acc[u][7] + bias[7];
        *(float4*)(g_GI1 + base)     = o1;
        *(float4*)(g_GI1 + base + 4) = o2;
    }
}

// ---------------- persistent recurrence kernel, 2-D (n, j) tiling ----------------
__global__ void __launch_bounds__(256, 1) rnn_persist(
    const float* __restrict__ Whe, const float* __restrict__ bhe,
    const float* __restrict__ Whd, const float* __restrict__ Wid,
    const float* __restrict__ bhd, float* __restrict__ out)
{
    extern __shared__ float sm[];
    float* sw = sm;                       // 48 * WST floats (weights)
    float* sh = sm + 48 * WST;            // enc: 32*HST ; dec: two 64*DST buffers
    float* sd0 = sh;
    float* sd1 = sh + 64 * DST;

    const int tid = threadIdx.x;
    const int cta = blockIdx.x;

    const float* hin  = g_hA;
    float*       hout = g_hB;
    unsigned epoch = 1;

    // =================== ENCODER: 4 n-groups x 32 j-groups ===================
    {
        const int gn = cta >> 5;          // 0..3
        const int gj = cta & 31;          // 0..31
        const int nbase = gn * 32;
        const int jbase = gj * 16;
        const int n_l = tid >> 3;
        const int q   = tid & 7;
        const int ng  = nbase + n_l;

        // 48 weight rows: row r = g*16 + j
        #pragma unroll
        for (int l = 0; l < 96; l++) {
            int idx = tid + 256 * l;
            int r = idx >> 9, k = idx & 511;
            int g = r >> 4, j = r & 15;
            sw[r * WST + k] = Whe[((size_t)(g * 512 + jbase + j)) * 512 + k];
        }
        float bias[2][3];
        float gi[2][3];
        #pragma unroll
        for (int js = 0; js < 2; js++)
            #pragma unroll
            for (int g = 0; g < 3; g++)
                bias[js][g] = bhe[g * 512 + jbase + q + 8 * js];

        const float* wp[6];
        #pragma unroll
        for (int g = 0; g < 3; g++)
            #pragma unroll
            for (int js = 0; js < 2; js++)
                wp[g * 2 + js] = sw + (g * 16 + q + 8 * js) * WST;
        __syncthreads();

        for (int t = 0; t < TENC; t++) {
            const float* gp = g_GI0 + ((size_t)t * NSEQ + ng) * G3 + jbase;
            #pragma unroll
            for (int js = 0; js < 2; js++)
                #pragma unroll
                for (int g = 0; g < 3; g++)
                    gi[js][g] = __ldg(gp + g * 512 + q + 8 * js);

            // stage h slice: 32 rows x 512 floats
            #pragma unroll
            for (int l = 0; l < 16; l++) {
                int g4 = tid + 256 * l;
                int row = g4 >> 7, col = (g4 & 127) * 4;
                *(float4*)(sh + row * HST + col) =
                    *(const float4*)(hin + (size_t)(nbase + row) * 512 + col);
            }
            __syncthreads();

            unsigned long long acc[6] = {0ull,0ull,0ull,0ull,0ull,0ull};
            const float* hrow = sh + n_l * HST;
            #pragma unroll 4
            for (int k = 0; k < 512; k += 4) {
                double2 h2 = *(const double2*)(hrow + k);
                #pragma unroll
                for (int r = 0; r < 6; r++) {
                    double2 w2 = *(const double2*)(wp[r] + k);
                    fma2(acc[r], h2.x, w2.x);
                    fma2(acc[r], h2.y, w2.y);
                }
            }

            #pragma unroll
            for (int js = 0; js < 2; js++) {
                int jh = jbase + q + 8 * js;
                float hr = pairsum(acc[0 * 2 + js]) + bias[js][0];
                float hz = pairsum(acc[1 * 2 + js]) + bias[js][1];
                float hn = pairsum(acc[2 * 2 + js]) + bias[js][2];
                float r = sigmoidf_(gi[js][0] + hr);
                float z = sigmoidf_(gi[js][1] + hz);
                float nn = tanhf(gi[js][2] + r * hn);
                float hold = hrow[jh];
                hout[(size_t)ng * 512 + jh] = (1.f - z) * nn + z * hold;
            }

            // last enc step: FULL barrier (decoder regroups n differently)
            if (t < TENC - 1) step_barrier(gn * 32, 32, epoch);
            else              step_barrier(0, 128, epoch);
            epoch++;
            const float* tmp = hin; hin = hout; hout = (float*)tmp;
        }
    }

    // =================== DECODER: 2 n-groups x 64 j-groups ===================
    {
        const int gn = cta >> 6;          // 0..1
        const int gj = cta & 63;          // 0..63
        const int nbase = gn * 64;
        const int jbase = gj * 8;
        const int n_l = tid >> 2;
        const int q   = tid & 3;
        const int ng  = nbase + n_l;

        // 48 weight rows: r = mat*24 + g*8 + j  (mat0 = Whh_dec, mat1 = Wih_dec left half)
        #pragma unroll
        for (int l = 0; l < 96; l++) {
            int idx = tid + 256 * l;
            int r = idx >> 9, k = idx & 511;
            int mat = r >= 24;
            int rr = mat ? r - 24 : r;
            int g = rr >> 3, j = rr & 7;
            int row = g * 512 + jbase + j;
            float v = mat ? Wid[(size_t)row * CIN + k]
                          : Whd[(size_t)row * 512 + k];
            sw[r * WST + k] = v;
        }
        float bias[2][3];
        #pragma unroll
        for (int js = 0; js < 2; js++)
            #pragma unroll
            for (int g = 0; g < 3; g++)
                bias[js][g] = bhd[g * 512 + jbase + q + 4 * js];

        const float* wp[12];
        #pragma unroll
        for (int mat = 0; mat < 2; mat++)
            #pragma unroll
            for (int g = 0; g < 3; g++)
                #pragma unroll
                for (int js = 0; js < 2; js++)
                    wp[(mat * 3 + g) * 2 + js] = sw + (mat * 24 + g * 8 + q + 4 * js) * WST;
        __syncthreads();

        for (int t = 0; t < TDEC; t++) {
            const float* gp = g_GI1 + ((size_t)t * NSEQ + ng) * G3 + jbase;
            float gi[2][3], hold[2];
            #pragma unroll
            for (int js = 0; js < 2; js++) {
                #pragma unroll
                for (int g = 0; g < 3; g++)
                    gi[js][g] = __ldg(gp + g * 512 + q + 4 * js);
                hold[js] = hin[(size_t)ng * 512 + jbase + q + 4 * js];
            }

            unsigned long long acc[12];
            #pragma unroll
            for (int r = 0; r < 12; r++) acc[r] = 0ull;

            // stage chunk 0 (64 rows x 128 k)
            float4 pr[8];
            #pragma unroll
            for (int l = 0; l < 8; l++) {
                int g4 = tid + 256 * l;
                pr[l] = *(const float4*)(hin + (size_t)(nbase + (g4 >> 5)) * 512 + (g4 & 31) * 4);
            }
            #pragma unroll
            for (int l = 0; l < 8; l++) {
                int g4 = tid + 256 * l;
                *(float4*)(sd0 + (g4 >> 5) * DST + (g4 & 31) * 4) = pr[l];
            }
            __syncthreads();

            #pragma unroll
            for (int c = 0; c < 4; c++) {
                const float* shc = (c & 1) ? sd1 : sd0;
                float*       shn = (c & 1) ? sd0 : sd1;
                int k0 = c * 128;
                if (c < 3) {
                    #pragma unroll
                    for (int l = 0; l < 8; l++) {
                        int g4 = tid + 256 * l;
                        pr[l] = *(const float4*)(hin + (size_t)(nbase + (g4 >> 5)) * 512 +
                                                 (k0 + 128) + (g4 & 31) * 4);
                    }
                }
                const float* hrow = shc + n_l * DST;
                #pragma unroll 2
                for (int k = 0; k < 128; k += 4) {
                    double2 h2 = *(const double2*)(hrow + k);
                    #pragma unroll
                    for (int r = 0; r < 12; r++) {
                        double2 w2 = *(const double2*)(wp[r] + k0 + k);
                        fma2(acc[r], h2.x, w2.x);
                        fma2(acc[r], h2.y, w2.y);
                    }
                }
                if (c < 3) {
                    #pragma unroll
                    for (int l = 0; l < 8; l++) {
                        int g4 = tid + 256 * l;
                        *(float4*)(shn + (g4 >> 5) * DST + (g4 & 31) * 4) = pr[l];
                    }
                }
                __syncthreads();
            }

            int a = ng & 63;
            int iph = ng >> 6;
            #pragma unroll
            for (int js = 0; js < 2; js++) {
                int jh = jbase + q + 4 * js;
                float aH0 = pairsum(acc[(0 * 3 + 0) * 2 + js]) + bias[js][0];
                float aH1 = pairsum(acc[(0 * 3 + 1) * 2 + js]) + bias[js][1];
                float aH2 = pairsum(acc[(0 * 3 + 2) * 2 + js]) + bias[js][2];
                float aI0 = pairsum(acc[(1 * 3 + 0) * 2 + js]);
                float aI1 = pairsum(acc[(1 * 3 + 1) * 2 + js]);
                float aI2 = pairsum(acc[(1 * 3 + 2) * 2 + js]);
                float r = sigmoidf_(gi[js][0] + aI0 + aH0);
                float z = sigmoidf_(gi[js][1] + aI1 + aH1);
                float nn = tanhf(gi[js][2] + aI2 + r * aH2);
                float hnew = (1.f - z) * nn + z * hold[js];
                hout[(size_t)ng * 512 + jh] = hnew;
                out[((size_t)a * HID + jh) * 96 + 2 * t + iph] = hnew;
            }

            if (t < TDEC - 1) {
                step_barrier(gn * 64, 64, epoch);
                epoch++;
                const float* tmp = hin; hin = hout; hout = (float*)tmp;
            }
        }
    }
}

// ---------------- launch ----------------
extern "C" void kernel_launch(void* const* d_in, const int* in_sizes, int n_in,
                              void* d_out, int out_size) {
    const float* X0  = (const float*)d_in[0];
    const float* X1  = (const float*)d_in[1];
    const float* Wie = (const float*)d_in[3];
    const float* Whe = (const float*)d_in[4];
    const float* bie = (const float*)d_in[5];
    const float* bhe = (const float*)d_in[6];
    const float* Wid = (const float*)d_in[7];
    const float* Whd = (const float*)d_in[8];
    const float* bid = (const float*)d_in[9];
    const float* bhd = (const float*)d_in[10];
    float* out = (float*)d_out;

    // smem: weights 48*516 + max(enc h 32*516, dec 2*64*132) floats
    int hfloats = (32 * HST > 2 * 64 * DST) ? 32 * HST : 2 * 64 * DST;
    const int SMEM_P = (48 * WST + hfloats) * 4;
    cudaFuncSetAttribute(rnn_persist, cudaFuncAttributeMaxDynamicSharedMemorySize, SMEM_P);

    dim3 tb(32, 8);
    transpose_w<<<dim3(CIN / 32, G3 / 32), tb>>>(Wie, 0);
    transpose_w<<<dim3(HID / 32, G3 / 32), tb>>>(Wid, 1);
    zero_h<<<256, 256>>>();
    gemm_enc<<<dim3(G3 / 128, (BATCH * 512) / 128), 256>>>(X0, bie);
    gemm_dec<<<dim3(G3 / 128, (BATCH * 96) / 128), 256>>>(X1, bid);

    rnn_persist<<<128, 256, SMEM_P>>>(Whe, bhe, Whd, Wid, bhd, out);
}

// round 5
// speedup vs baseline: 1.7973x; 1.7973x over previous
#include <cuda_runtime.h>
#include <math.h>

#define HID   512
#define BATCH 64
#define NSEQ  128
#define TENC  256
#define TDEC  48
#define G3    1536   // 3*H
#define CIN   1024   // 2*H

#define WST 516      // weight row stride (floats); 516%32=4 -> conflict-free row banks
#define HST 516      // enc h row stride
#define DST 132      // dec h chunk row stride; 132%32=4

// ---------------- scratch ----------------
__device__ float g_GI0[(size_t)TENC * NSEQ * G3];
__device__ float g_GI1[(size_t)TDEC * NSEQ * G3];
__device__ float g_WeT[(size_t)CIN * G3];
__device__ float g_WdT[(size_t)HID * G3];
__device__ float g_hA[NSEQ * HID];
__device__ float g_hB[NSEQ * HID];
__device__ unsigned g_cnt[8 * 32];   // one counter per 128B line; cids 0..7

// ---------------- helpers ----------------
__device__ __forceinline__ void fma2(unsigned long long& acc, double a, double b) {
    asm("fma.rn.f32x2 %0, %1, %2, %0;"
        : "+l"(acc)
        : "l"(__double_as_longlong(a)), "l"(__double_as_longlong(b)));
}
__device__ __forceinline__ float pairsum(unsigned long long v) {
    return __uint_as_float((unsigned)v) + __uint_as_float((unsigned)(v >> 32));
}
__device__ __forceinline__ float sigmoidf_(float x) { return 1.f / (1.f + expf(-x)); }

// monotonic counter barrier: 1 atomic arrive / CTA, 1 polling thread / CTA
__device__ __forceinline__ void bar_arrive(int cid) {
    __syncthreads();
    if (threadIdx.x == 0) {
        __threadfence();                     // release: h stores visible before count
        atomicAdd(&g_cnt[cid * 32], 1u);
    }
}
__device__ __forceinline__ void bar_wait(int cid, unsigned target) {
    if (threadIdx.x == 0) {
        const unsigned* p = &g_cnt[cid * 32];
        for (;;) {
            unsigned v;
            asm volatile("ld.relaxed.gpu.global.u32 %0, [%1];" : "=r"(v) : "l"(p) : "memory");
            if (v >= target) break;
            __nanosleep(32);
        }
        __threadfence();                     // acquire: invalidate L1, order later reads
    }
    __syncthreads();
}

// ---------------- weight transpose ----------------
__global__ void transpose_w(const float* __restrict__ src, int which) {
    __shared__ float tile[32][33];
    float* dst = which ? g_WdT : g_WeT;
    int cOff   = which ? 512 : 0;
    int c0 = blockIdx.x * 32, j0 = blockIdx.y * 32;
    int x = threadIdx.x, y = threadIdx.y;
    #pragma unroll
    for (int yy = y; yy < 32; yy += 8)
        tile[yy][x] = src[(size_t)(j0 + yy) * CIN + cOff + c0 + x];
    __syncthreads();
    #pragma unroll
    for (int yy = y; yy < 32; yy += 8)
        dst[(size_t)(c0 + yy) * G3 + j0 + x] = tile[x][yy];
}

__global__ void zero_h() {
    int i = blockIdx.x * 256 + threadIdx.x;
    if (i < NSEQ * HID) g_hA[i] = 0.f;
    if (i < 8 * 32) g_cnt[i] = 0u;
}

// ---------------- encoder GI GEMM ----------------
__global__ void __launch_bounds__(256) gemm_enc(const float* __restrict__ X0,
                                                const float* __restrict__ bih) {
    __shared__ float As[16][128];
    __shared__ float Bs[16][128];
    int m0 = blockIdx.y * 128, j0 = blockIdx.x * 128;
    int tid = threadIdx.x;
    int tx = tid & 15, ty = tid >> 4;
    int bb = m0 >> 9;
    int t0base = m0 & 511;
    float acc[8][8];
    #pragma unroll
    for (int u = 0; u < 8; u++)
        #pragma unroll
        for (int v = 0; v < 8; v++) acc[u][v] = 0.f;

    for (int c0 = 0; c0 < CIN; c0 += 16) {
        #pragma unroll
        for (int l = 0; l < 2; l++) {
            int idx4 = tid + 256 * l;
            int mm4 = idx4 & 31, cc = idx4 >> 5;
            float4 va = *(const float4*)(X0 + ((size_t)(bb * CIN + c0 + cc)) * 512 + t0base + mm4 * 4);
            *(float4*)(&As[cc][mm4 * 4]) = va;
            float4 vb = *(const float4*)(g_WeT + (size_t)(c0 + cc) * G3 + j0 + mm4 * 4);
            *(float4*)(&Bs[cc][mm4 * 4]) = vb;
        }
        __syncthreads();
        #pragma unroll
        for (int k = 0; k < 16; k++) {
            float a[8], bv[8];
            #pragma unroll
            for (int u = 0; u < 8; u++) a[u] = As[k][ty * 8 + u];
            #pragma unroll
            for (int v = 0; v < 8; v++) bv[v] = Bs[k][tx * 8 + v];
            #pragma unroll
            for (int u = 0; u < 8; u++)
                #pragma unroll
                for (int v = 0; v < 8; v++) acc[u][v] += a[u] * bv[v];
        }
        __syncthreads();
    }
    float bias[8];
    #pragma unroll
    for (int v = 0; v < 8; v++) bias[v] = bih[j0 + tx * 8 + v];
    #pragma unroll
    for (int u = 0; u < 8; u++) {
        int m = m0 + ty * 8 + u;
        int t0 = m & 511;
        int n = ((t0 & 1) << 6) | (m >> 9);
        size_t base = ((size_t)((t0 >> 1) * NSEQ + n)) * G3 + j0 + tx * 8;
        float4 o1, o2;
        o1.x = acc[u][0] + bias[0]; o1.y = acc[u][1] + bias[1];
        o1.z = acc[u][2] + bias[2]; o1.w = acc[u][3] + bias[3];
        o2.x = acc[u][4] + bias[4]; o2.y = acc[u][5] + bias[5];
        o2.z = acc[u][6] + bias[6]; o2.w = acc[u][7] + bias[7];
        *(float4*)(g_GI0 + base)     = o1;
        *(float4*)(g_GI0 + base + 4) = o2;
    }
}

// ---------------- decoder GI GEMM ----------------
__global__ void __launch_bounds__(256) gemm_dec(const float* __restrict__ X1,
                                                const float* __restrict__ bih) {
    __shared__ float As[16][128];
    __shared__ float Bs[16][128];
    int m0 = blockIdx.y * 128, j0 = blockIdx.x * 128;
    int tid = threadIdx.x;
    int tx = tid & 15, ty = tid >> 4;
    float acc[8][8];
    #pragma unroll
    for (int u = 0; u < 8; u++)
        #pragma unroll
        for (int v = 0; v < 8; v++) acc[u][v] = 0.f;

    for (int c0 = 0; c0 < HID; c0 += 16) {
        #pragma unroll
        for (int l = 0; l < 8; l++) {
            int idx = tid + 256 * l;
            int r = idx & 127, cc = idx >> 7;
            int m = m0 + r;
            int b = m / 96;
            int t0 = m - b * 96;
            As[cc][r] = X1[((size_t)(b * HID + c0 + cc)) * 96 + t0];
        }
        #pragma unroll
        for (int l = 0; l < 2; l++) {
            int idx4 = tid + 256 * l;
            int jj4 = idx4 & 31, cc = idx4 >> 5;
            float4 vb = *(const float4*)(g_WdT + (size_t)(c0 + cc) * G3 + j0 + jj4 * 4);
            *(float4*)(&Bs[cc][jj4 * 4]) = vb;
        }
        __syncthreads();
        #pragma unroll
        for (int k = 0; k < 16; k++) {
            float a[8], bv[8];
            #pragma unroll
            for (int u = 0; u < 8; u++) a[u] = As[k][ty * 8 + u];
            #pragma unroll
            for (int v = 0; v < 8; v++) bv[v] = Bs[k][tx * 8 + v];
            #pragma unroll
            for (int u = 0; u < 8; u++)
                #pragma unroll
                for (int v = 0; v < 8; v++) acc[u][v] += a[u] * bv[v];
        }
        __syncthreads();
    }
    float bias[8];
    #pragma unroll
    for (int v = 0; v < 8; v++) bias[v] = bih[j0 + tx * 8 + v];
    #pragma unroll
    for (int u = 0; u < 8; u++) {
        int m = m0 + ty * 8 + u;
        int b = m / 96;
        int t0 = m - b * 96;
        int n = ((t0 & 1) << 6) | b;
        size_t base = ((size_t)((t0 >> 1) * NSEQ + n)) * G3 + j0 + tx * 8;
        float4 o1, o2;
        o1.x = acc[u][0] + bias[0]; o1.y = acc[u][1] + bias[1];
        o1.z = acc[u][2] + bias[2]; o1.w = acc[u][3] + bias[3];
        o2.x = acc[u][4] + bias[4]; o2.y = acc[u][5] + bias[5];
        o2.z = acc[u][6] + bias[6]; o2.w = acc[u][7] + bias[7];
        *(float4*)(g_GI1 + base)     = o1;
        *(float4*)(g_GI1 + base + 4) = o2;
    }
}

// ---------------- persistent recurrence kernel, 2-D (n, j) tiling ----------------
__global__ void __launch_bounds__(256, 1) rnn_persist(
    const float* __restrict__ Whe, const float* __restrict__ bhe,
    const float* __restrict__ Whd, const float* __restrict__ Wid,
    const float* __restrict__ bhd, float* __restrict__ out)
{
    extern __shared__ float sm[];
    float* sw = sm;                       // 48 * WST floats (weights)
    float* sh = sm + 48 * WST;            // enc: 32*HST ; dec: two 64*DST buffers
    float* sd0 = sh;
    float* sd1 = sh + 64 * DST;

    const int tid = threadIdx.x;
    const int cta = blockIdx.x;

    const float* hin  = g_hA;
    float*       hout = g_hB;

    // =================== ENCODER: 4 n-groups x 32 j-groups ===================
    {
        const int gn = cta >> 5;          // 0..3 -> barrier cid gn
        const int gj = cta & 31;          // 0..31
        const int nbase = gn * 32;
        const int jbase = gj * 16;
        const int n_l = tid >> 3;
        const int q   = tid & 7;
        const int ng  = nbase + n_l;

        // 48 weight rows: row r = g*16 + j
        #pragma unroll
        for (int l = 0; l < 96; l++) {
            int idx = tid + 256 * l;
            int r = idx >> 9, k = idx & 511;
            int g = r >> 4, j = r & 15;
            sw[r * WST + k] = Whe[((size_t)(g * 512 + jbase + j)) * 512 + k];
        }
        float bias[2][3];
        #pragma unroll
        for (int js = 0; js < 2; js++)
            #pragma unroll
            for (int g = 0; g < 3; g++)
                bias[js][g] = bhe[g * 512 + jbase + q + 8 * js];

        const float* wp[6];
        #pragma unroll
        for (int g = 0; g < 3; g++)
            #pragma unroll
            for (int js = 0; js < 2; js++)
                wp[g * 2 + js] = sw + (g * 16 + q + 8 * js) * WST;
        __syncthreads();

        // GI prefetch for t=0; h_prev carried in registers (h starts at 0)
        float gi[2][3];
        {
            const float* gp = g_GI0 + (size_t)ng * G3 + jbase;
            #pragma unroll
            for (int js = 0; js < 2; js++)
                #pragma unroll
                for (int g = 0; g < 3; g++)
                    gi[js][g] = __ldg(gp + g * 512 + q + 8 * js);
        }
        float h_prev[2] = {0.f, 0.f};

        for (int t = 0; t < TENC; t++) {
            // stage h slice: 32 rows x 512 floats
            #pragma unroll
            for (int l = 0; l < 16; l++) {
                int g4 = tid + 256 * l;
                int row = g4 >> 7, col = (g4 & 127) * 4;
                *(float4*)(sh + row * HST + col) =
                    *(const float4*)(hin + (size_t)(nbase + row) * 512 + col);
            }
            __syncthreads();

            unsigned long long acc[6] = {0ull,0ull,0ull,0ull,0ull,0ull};
            const float* hrow = sh + n_l * HST;
            #pragma unroll 4
            for (int k = 0; k < 512; k += 4) {
                double2 h2 = *(const double2*)(hrow + k);
                #pragma unroll
                for (int r = 0; r < 6; r++) {
                    double2 w2 = *(const double2*)(wp[r] + k);
                    fma2(acc[r], h2.x, w2.x);
                    fma2(acc[r], h2.y, w2.y);
                }
            }

            #pragma unroll
            for (int js = 0; js < 2; js++) {
                int jh = jbase + q + 8 * js;
                float hr = pairsum(acc[0 * 2 + js]) + bias[js][0];
                float hz = pairsum(acc[1 * 2 + js]) + bias[js][1];
                float hn = pairsum(acc[2 * 2 + js]) + bias[js][2];
                float r = sigmoidf_(gi[js][0] + hr);
                float z = sigmoidf_(gi[js][1] + hz);
                float nn = tanhf(gi[js][2] + r * hn);
                float hnew = (1.f - z) * nn + z * h_prev[js];
                h_prev[js] = hnew;
                hout[(size_t)ng * 512 + jh] = hnew;
            }

            // arrive, overlap next-step GI prefetch with other CTAs' arrival, then wait
            int cid      = (t < TENC - 1) ? gn : 4;
            unsigned tgt = (t < TENC - 1) ? 32u * (unsigned)(t + 1) : 128u;
            bar_arrive(cid);
            if (t + 1 < TENC) {
                const float* gp = g_GI0 + ((size_t)(t + 1) * NSEQ + ng) * G3 + jbase;
                #pragma unroll
                for (int js = 0; js < 2; js++)
                    #pragma unroll
                    for (int g = 0; g < 3; g++)
                        gi[js][g] = __ldg(gp + g * 512 + q + 8 * js);
            }
            bar_wait(cid, tgt);

            const float* tmp = hin; hin = hout; hout = (float*)tmp;
        }
    }

    // =================== DECODER: 2 n-groups x 64 j-groups ===================
    {
        const int gn = cta >> 6;          // 0..1 -> barrier cid 5+gn
        const int gj = cta & 63;          // 0..63
        const int nbase = gn * 64;
        const int jbase = gj * 8;
        const int n_l = tid >> 2;
        const int q   = tid & 3;
        const int ng  = nbase + n_l;

        // 48 weight rows: r = mat*24 + g*8 + j (mat0 = Whh_dec, mat1 = Wih_dec left half)
        #pragma unroll
        for (int l = 0; l < 96; l++) {
            int idx = tid + 256 * l;
            int r = idx >> 9, k = idx & 511;
            int mat = r >= 24;
            int rr = mat ? r - 24 : r;
            int g = rr >> 3, j = rr & 7;
            int row = g * 512 + jbase + j;
            float v = mat ? Wid[(size_t)row * CIN + k]
                          : Whd[(size_t)row * 512 + k];
            sw[r * WST + k] = v;
        }
        float bias[2][3];
        #pragma unroll
        for (int js = 0; js < 2; js++)
            #pragma unroll
            for (int g = 0; g < 3; g++)
                bias[js][g] = bhd[g * 512 + jbase + q + 4 * js];

        const float* wp[12];
        #pragma unroll
        for (int mat = 0; mat < 2; mat++)
            #pragma unroll
            for (int g = 0; g < 3; g++)
                #pragma unroll
                for (int js = 0; js < 2; js++)
                    wp[(mat * 3 + g) * 2 + js] = sw + (mat * 24 + g * 8 + q + 4 * js) * WST;
        __syncthreads();

        // GI prefetch t=0; h_prev from encoder final state (one-time read)
        float gi[2][3], h_prev[2];
        {
            const float* gp = g_GI1 + (size_t)ng * G3 + jbase;
            #pragma unroll
            for (int js = 0; js < 2; js++) {
                #pragma unroll
                for (int g = 0; g < 3; g++)
                    gi[js][g] = __ldg(gp + g * 512 + q + 4 * js);
                h_prev[js] = hin[(size_t)ng * 512 + jbase + q + 4 * js];
            }
        }

        for (int t = 0; t < TDEC; t++) {
            unsigned long long acc[12];
            #pragma unroll
            for (int r = 0; r < 12; r++) acc[r] = 0ull;

            // stage chunk 0 (64 rows x 128 k)
            float4 pr[8];
            #pragma unroll
            for (int l = 0; l < 8; l++) {
                int g4 = tid + 256 * l;
                pr[l] = *(const float4*)(hin + (size_t)(nbase + (g4 >> 5)) * 512 + (g4 & 31) * 4);
            }
            #pragma unroll
            for (int l = 0; l < 8; l++) {
                int g4 = tid + 256 * l;
                *(float4*)(sd0 + (g4 >> 5) * DST + (g4 & 31) * 4) = pr[l];
            }
            __syncthreads();

            #pragma unroll
            for (int c = 0; c < 4; c++) {
                const float* shc = (c & 1) ? sd1 : sd0;
                float*       shn = (c & 1) ? sd0 : sd1;
                int k0 = c * 128;
                if (c < 3) {
                    #pragma unroll
                    for (int l = 0; l < 8; l++) {
                        int g4 = tid + 256 * l;
                        pr[l] = *(const float4*)(hin + (size_t)(nbase + (g4 >> 5)) * 512 +
                                                 (k0 + 128) + (g4 & 31) * 4);
                    }
                }
                const float* hrow = shc + n_l * DST;
                #pragma unroll 2
                for (int k = 0; k < 128; k += 4) {
                    double2 h2 = *(const double2*)(hrow + k);
                    #pragma unroll
                    for (int r = 0; r < 12; r++) {
                        double2 w2 = *(const double2*)(wp[r] + k0 + k);
                        fma2(acc[r], h2.x, w2.x);
                        fma2(acc[r], h2.y, w2.y);
                    }
                }
                if (c < 3) {
                    #pragma unroll
                    for (int l = 0; l < 8; l++) {
                        int g4 = tid + 256 * l;
                        *(float4*)(shn + (g4 >> 5) * DST + (g4 & 31) * 4) = pr[l];
                    }
                }
                __syncthreads();
            }

            int a = ng & 63;
            int iph = ng >> 6;
            #pragma unroll
            for (int js = 0; js < 2; js++) {
                int jh = jbase + q + 4 * js;
                float aH0 = pairsum(acc[(0 * 3 + 0) * 2 + js]) + bias[js][0];
                float aH1 = pairsum(acc[(0 * 3 + 1) * 2 + js]) + bias[js][1];
                float aH2 = pairsum(acc[(0 * 3 + 2) * 2 + js]) + bias[js][2];
                float aI0 = pairsum(acc[(1 * 3 + 0) * 2 + js]);
                float aI1 = pairsum(acc[(1 * 3 + 1) * 2 + js]);
                float aI2 = pairsum(acc[(1 * 3 + 2) * 2 + js]);
                float r = sigmoidf_(gi[js][0] + aI0 + aH0);
                float z = sigmoidf_(gi[js][1] + aI1 + aH1);
                float nn = tanhf(gi[js][2] + aI2 + r * aH2);
                float hnew = (1.f - z) * nn + z * h_prev[js];
                h_prev[js] = hnew;
                hout[(size_t)ng * 512 + jh] = hnew;
                out[((size_t)a * HID + jh) * 96 + 2 * t + iph] = hnew;
            }

            if (t < TDEC - 1) {
                bar_arrive(5 + gn);
                {
                    const float* gp = g_GI1 + ((size_t)(t + 1) * NSEQ + ng) * G3 + jbase;
                    #pragma unroll
                    for (int js = 0; js < 2; js++)
                        #pragma unroll
                        for (int g = 0; g < 3; g++)
                            gi[js][g] = __ldg(gp + g * 512 + q + 4 * js);
                }
                bar_wait(5 + gn, 64u * (unsigned)(t + 1));
                const float* tmp = hin; hin = hout; hout = (float*)tmp;
            }
        }
    }
}

// ---------------- launch ----------------
extern "C" void kernel_launch(void* const* d_in, const int* in_sizes, int n_in,
                              void* d_out, int out_size) {
    const float* X0  = (const float*)d_in[0];
    const float* X1  = (const float*)d_in[1];
    const float* Wie = (const float*)d_in[3];
    const float* Whe = (const float*)d_in[4];
    const float* bie = (const float*)d_in[5];
    const float* bhe = (const float*)d_in[6];
    const float* Wid = (const float*)d_in[7];
    const float* Whd = (const float*)d_in[8];
    const float* bid = (const float*)d_in[9];
    const float* bhd = (const float*)d_in[10];
    float* out = (float*)d_out;

    int hfloats = (32 * HST > 2 * 64 * DST) ? 32 * HST : 2 * 64 * DST;
    const int SMEM_P = (48 * WST + hfloats) * 4;
    cudaFuncSetAttribute(rnn_persist, cudaFuncAttributeMaxDynamicSharedMemorySize, SMEM_P);

    dim3 tb(32, 8);
    transpose_w<<<dim3(CIN / 32, G3 / 32), tb>>>(Wie, 0);
    transpose_w<<<dim3(HID / 32, G3 / 32), tb>>>(Wid, 1);
    zero_h<<<256, 256>>>();
    gemm_enc<<<dim3(G3 / 128, (BATCH * 512) / 128), 256>>>(X0, bie);
    gemm_dec<<<dim3(G3 / 128, (BATCH * 96) / 128), 256>>>(X1, bid);

    rnn_persist<<<128, 256, SMEM_P>>>(Whe, bhe, Whd, Wid, bhd, out);
}

// round 7
// speedup vs baseline: 2.3870x; 1.3281x over previous
#include <cuda_runtime.h>
#include <cuda_bf16.h>
#include <math.h>
#include <stdint.h>

#define HID   512
#define BATCH 64
#define NSEQ  128
#define TENC  256
#define TDEC  48
#define G3    1536   // 3*H
#define CIN   1024   // 2*H

#define SW_STRIDE 520   // persist: weight row stride
#define SH_STRIDE 68    // persist: h row stride

// ---------------- scratch ----------------
__device__ __align__(16) float g_GI0[(size_t)TENC * NSEQ * G3];
__device__ __align__(16) float g_GI1[(size_t)TDEC * NSEQ * G3];
__device__ __align__(16) __nv_bfloat16 g_Ah[(size_t)32768 * 1024];
__device__ __align__(16) __nv_bfloat16 g_Al[(size_t)32768 * 1024];
__device__ __align__(16) __nv_bfloat16 g_A1h[(size_t)6144 * 512];
__device__ __align__(16) __nv_bfloat16 g_A1l[(size_t)6144 * 512];
__device__ __align__(16) __nv_bfloat16 g_Bh[(size_t)1536 * 1024];
__device__ __align__(16) __nv_bfloat16 g_Bl[(size_t)1536 * 1024];
__device__ __align__(16) __nv_bfloat16 g_B1h[(size_t)1536 * 512];
__device__ __align__(16) __nv_bfloat16 g_B1l[(size_t)1536 * 512];
__device__ float g_hA[NSEQ * HID];
__device__ float g_hB[NSEQ * HID];
__device__ unsigned g_bar_count = 0;
__device__ unsigned g_bar_gen   = 0;

// ---------------- fp32x2 helpers (persist kernel) ----------------
__device__ __forceinline__ void fma2(unsigned long long& acc, double a, double b) {
    asm("fma.rn.f32x2 %0, %1, %2, %0;"
        : "+l"(acc)
        : "l"(__double_as_longlong(a)), "l"(__double_as_longlong(b)));
}
__device__ __forceinline__ float pairsum(unsigned long long v) {
    return __uint_as_float((unsigned)v) + __uint_as_float((unsigned)(v >> 32));
}
__device__ __forceinline__ float sigmoidf_(float x) { return 1.f / (1.f + expf(-x)); }

// ---------------- grid barrier (round-2, empirically best) ----------------
__device__ __forceinline__ void grid_barrier() {
    __syncthreads();
    if (threadIdx.x == 0) {
        unsigned g0 = atomicAdd(&g_bar_gen, 0u);
        __threadfence();
        if (atomicAdd(&g_bar_count, 1u) == gridDim.x - 1) {
            g_bar_count = 0;
            __threadfence();
            atomicAdd(&g_bar_gen, 1u);
        } else {
            while (atomicAdd(&g_bar_gen, 0u) == g0) { }
        }
        __threadfence();
    }
    __syncthreads();
}

// ---------------- mma/ldmatrix/cp.async helpers (portable ISA) ----------------
__device__ __forceinline__ uint32_t smem_u32(const void* p) {
    uint32_t a;
    asm("{ .reg .u64 t; cvta.to.shared.u64 t, %1; cvt.u32.u64 %0, t; }" : "=r"(a) : "l"(p));
    return a;
}
__device__ __forceinline__ void ldsm4(uint32_t* r, uint32_t a) {
    asm volatile("ldmatrix.sync.aligned.m8n8.x4.shared.b16 {%0,%1,%2,%3}, [%4];"
                 : "=r"(r[0]), "=r"(r[1]), "=r"(r[2]), "=r"(r[3]) : "r"(a));
}
__device__ __forceinline__ void mma_bf(float* d, const uint32_t* a, uint32_t b0, uint32_t b1) {
    asm volatile("mma.sync.aligned.m16n8k16.row.col.f32.bf16.bf16.f32 "
                 "{%0,%1,%2,%3}, {%4,%5,%6,%7}, {%8,%9}, {%0,%1,%2,%3};"
                 : "+f"(d[0]), "+f"(d[1]), "+f"(d[2]), "+f"(d[3])
                 : "r"(a[0]), "r"(a[1]), "r"(a[2]), "r"(a[3]), "r"(b0), "r"(b1));
}
__device__ __forceinline__ void cpasync16(uint32_t s, const void* g) {
    asm volatile("cp.async.cg.shared.global [%0], [%1], 16;" :: "r"(s), "l"(g));
}
#define CP_COMMIT() asm volatile("cp.async.commit_group;")
#define CP_WAIT(n)  asm volatile("cp.async.wait_group %0;" :: "n"(n))

// ---------------- conversion kernels ----------------
// X0[b][c][t] fp32 -> Ah/Al[m=b*512+t][k=c] bf16 hi/lo (K-major)
__global__ void conv_x0(const float* __restrict__ X0) {
    __shared__ float tile[32][33];
    int t0 = blockIdx.x * 32, c0 = blockIdx.y * 32, b = blockIdx.z;
    int x = threadIdx.x, y = threadIdx.y;
    #pragma unroll
    for (int yy = y; yy < 32; yy += 8)
        tile[yy][x] = X0[((size_t)(b * 1024 + c0 + yy)) * 512 + t0 + x];
    __syncthreads();
    #pragma unroll
    for (int yy = y; yy < 32; yy += 8) {
        float v = tile[x][yy];
        __nv_bfloat16 hv = __float2bfloat16(v);
        __nv_bfloat16 lv = __float2bfloat16(v - __bfloat162float(hv));
        size_t idx = (size_t)(b * 512 + t0 + yy) * 1024 + c0 + x;
        g_Ah[idx] = hv;
        g_Al[idx] = lv;
    }
}

// X1[b][c][t] fp32 (T=96) -> A1h/A1l[m=b*96+t][k=c], K=512
__global__ void conv_x1(const float* __restrict__ X1) {
    __shared__ float tile[32][33];
    int t0 = blockIdx.x * 32, c0 = blockIdx.y * 32, b = blockIdx.z;
    int x = threadIdx.x, y = threadIdx.y;
    #pragma unroll
    for (int yy = y; yy < 32; yy += 8)
        tile[yy][x] = X1[((size_t)(b * 512 + c0 + yy)) * 96 + t0 + x];
    __syncthreads();
    #pragma unroll
    for (int yy = y; yy < 32; yy += 8) {
        float v = tile[x][yy];
        __nv_bfloat16 hv = __float2bfloat16(v);
        __nv_bfloat16 lv = __float2bfloat16(v - __bfloat162float(hv));
        size_t idx = (size_t)(b * 96 + t0 + yy) * 512 + c0 + x;
        g_A1h[idx] = hv;
        g_A1l[idx] = lv;
    }
}

// W[j][Kin] -> outh/outl[j][Kout], reading src[j*Kin + koff + k]
__global__ void conv_w(const float* __restrict__ src, __nv_bfloat16* outh, __nv_bfloat16* outl,
                       int Kout, int Kin, int koff, long total) {
    long i = (long)blockIdx.x * 256 + threadIdx.x;
    if (i >= total) return;
    long j = i / Kout, k = i - j * Kout;
    float v = src[j * Kin + koff + k];
    __nv_bfloat16 hv = __float2bfloat16(v);
    outh[i] = hv;
    outl[i] = __float2bfloat16(v - __bfloat162float(hv));
}

__global__ void zero_h() {
    int i = blockIdx.x * 256 + threadIdx.x;
    if (i < NSEQ * HID) g_hA[i] = 0.f;
}

// ---------------- mma.sync bf16x3 GI GEMM ----------------
// C[128m x 128j] = A·B^T (+bias): Ah·Bh + Ah·Bl + Al·Bh, fp32 accum.
// SMEM stage: 4 tiles (Ah, Al, Bh, Bl), each 128 rows x 32 k, padded stride 40 elems (80B).
// mode 0: scatter m=b*512+t0 -> GI0 ; mode 1: m=b*96+t0 -> GI1.
#define TILE_B   10240                      // bytes per padded tile
#define STAGE_B  (4 * TILE_B)               // 40960
#define GEMM_SMEM (2 * STAGE_B)             // 81920

__global__ void __launch_bounds__(256) gemm_mma(
    const __nv_bfloat16* __restrict__ Ah, const __nv_bfloat16* __restrict__ Al,
    const __nv_bfloat16* __restrict__ Bh, const __nv_bfloat16* __restrict__ Bl,
    const float* __restrict__ bias, float* __restrict__ outGI, int K, int mode)
{
    extern __shared__ char smem[];
    const uint32_t sb = smem_u32(smem);
    const int tid  = threadIdx.x;
    const int wid  = tid >> 5;
    const int lane = tid & 31;
    const int j0 = blockIdx.x * 128;
    const int m0 = blockIdx.y * 128;
    const int warpM = (wid & 3) * 32;
    const int warpN = (wid >> 2) * 64;

    float acc[2][8][4];
    #pragma unroll
    for (int mt = 0; mt < 2; mt++)
        #pragma unroll
        for (int f = 0; f < 8; f++)
            #pragma unroll
            for (int r = 0; r < 4; r++) acc[mt][f][r] = 0.f;

    const int NC = K >> 5;

    // chunk loader: 8 cp.async per thread (2 per tile)
    auto load_chunk = [&](int ch, int stage) {
        uint32_t base = sb + stage * STAGE_B;
        int c0 = ch * 32;
        #pragma unroll
        for (int i = 0; i < 2; i++) {
            int idx = tid + 256 * i;
            int r = idx >> 2, s = idx & 3;
            uint32_t soff = (uint32_t)(r * 80 + s * 16);
            size_t ga = (size_t)(m0 + r) * K + c0 + s * 8;
            size_t gb = (size_t)(j0 + r) * K + c0 + s * 8;
            cpasync16(base + 0 * TILE_B + soff, Ah + ga);
            cpasync16(base + 1 * TILE_B + soff, Al + ga);
            cpasync16(base + 2 * TILE_B + soff, Bh + gb);
            cpasync16(base + 3 * TILE_B + soff, Bl + gb);
        }
    };

    load_chunk(0, 0);
    CP_COMMIT();

    for (int ch = 0; ch < NC; ch++) {
        if (ch + 1 < NC) {
            load_chunk(ch + 1, (ch + 1) & 1);
            CP_COMMIT();
            CP_WAIT(1);
        } else {
            CP_WAIT(0);
        }
        __syncthreads();

        uint32_t base = sb + (ch & 1) * STAGE_B;
        #pragma unroll
        for (int k16 = 0; k16 < 2; k16++) {
            uint32_t koff = (uint32_t)(k16 * 32 + (lane >> 4) * 16);
            uint32_t ah[2][4], al[2][4];
            #pragma unroll
            for (int mt = 0; mt < 2; mt++) {
                uint32_t row = (uint32_t)(warpM + mt * 16 + (lane & 15));
                ldsm4(ah[mt], base + 0 * TILE_B + row * 80 + koff);
                ldsm4(al[mt], base + 1 * TILE_B + row * 80 + koff);
            }
            uint32_t bh[4][4], bl[4][4];
            #pragma unroll
            for (int bt = 0; bt < 4; bt++) {
                uint32_t row = (uint32_t)(warpN + bt * 16 + (lane & 15));
                ldsm4(bh[bt], base + 2 * TILE_B + row * 80 + koff);
                ldsm4(bl[bt], base + 3 * TILE_B + row * 80 + koff);
            }
            #pragma unroll
            for (int mt = 0; mt < 2; mt++)
                #pragma unroll
                for (int bt = 0; bt < 4; bt++) {
                    mma_bf(acc[mt][bt * 2 + 0], ah[mt], bh[bt][0], bh[bt][2]);
                    mma_bf(acc[mt][bt * 2 + 1], ah[mt], bh[bt][1], bh[bt][3]);
                    mma_bf(acc[mt][bt * 2 + 0], ah[mt], bl[bt][0], bl[bt][2]);
                    mma_bf(acc[mt][bt * 2 + 1], ah[mt], bl[bt][1], bl[bt][3]);
                    mma_bf(acc[mt][bt * 2 + 0], al[mt], bh[bt][0], bh[bt][2]);
                    mma_bf(acc[mt][bt * 2 + 1], al[mt], bh[bt][1], bh[bt][3]);
                }
        }
        __syncthreads();
    }

    // epilogue: bias + scatter (float2 stores)
    float2 bias2[8];
    #pragma unroll
    for (int bt = 0; bt < 4; bt++)
        #pragma unroll
        for (int hf = 0; hf < 2; hf++) {
            int j = j0 + warpN + bt * 16 + hf * 8 + (lane & 3) * 2;
            bias2[bt * 2 + hf] = make_float2(bias[j], bias[j + 1]);
        }

    size_t rb[4];
    #pragma unroll
    for (int mt = 0; mt < 2; mt++)
        #pragma unroll
        for (int u = 0; u < 2; u++) {
            int m = m0 + warpM + mt * 16 + u * 8 + (lane >> 2);
            int bb, t0;
            if (mode == 0) { t0 = m & 511; bb = m >> 9; }
            else           { bb = m / 96; t0 = m - bb * 96; }
            int n = ((t0 & 1) << 6) | bb;
            rb[mt * 2 + u] = ((size_t)((t0 >> 1) * NSEQ + n)) * G3;
        }

    #pragma unroll
    for (int mt = 0; mt < 2; mt++)
        #pragma unroll
        for (int bt = 0; bt < 4; bt++)
            #pragma unroll
            for (int hf = 0; hf < 2; hf++) {
                const float* ac = acc[mt][bt * 2 + hf];
                float2 bz = bias2[bt * 2 + hf];
                int jc = j0 + warpN + bt * 16 + hf * 8 + (lane & 3) * 2;
                float2 v0 = make_float2(ac[0] + bz.x, ac[1] + bz.y);
                float2 v1 = make_float2(ac[2] + bz.x, ac[3] + bz.y);
                *(float2*)(outGI + rb[mt * 2 + 0] + jc) = v0;
                *(float2*)(outGI + rb[mt * 2 + 1] + jc) = v1;
            }
}

// ---------------- persistent recurrence kernel (round-2, best measured) ----------------
__global__ void __launch_bounds__(256, 1) rnn_persist(
    const float* __restrict__ Whe, const float* __restrict__ bhe,
    const float* __restrict__ Whd, const float* __restrict__ Wid,
    const float* __restrict__ bhd, float* __restrict__ out)
{
    extern __shared__ float sm[];
    float* sw  = sm;                                  // 24 * 520
    float* sh0 = sm + 24 * SW_STRIDE;                 // 128 * 68
    float* sh1 = sh0 + 128 * SH_STRIDE;               // 128 * 68

    int tid = threadIdx.x;
    int jb  = blockIdx.x;
    int a   = tid >> 2;
    int b   = tid & 3;
    int n0  = a, n1 = a + 64;
    int jh  = jb * 4 + b;

    int s_nn = tid >> 4;
    int s_kq = tid & 15;

    #pragma unroll
    for (int l = 0; l < 24; l++) {
        int idx = tid + 256 * l;
        int q = idx >> 9, k = idx & 511;
        int j = jb * 4 + (q & 3) + (q >> 2) * 512;
        sw[q * SW_STRIDE + k] = Whe[(size_t)j * 512 + k];
    }
    float bias[3];
    #pragma unroll
    for (int g = 0; g < 3; g++) bias[g] = bhe[jh + 512 * g];
    __syncthreads();

    const float* wp0 = sw + b * SW_STRIDE;
    const float* wp1 = sw + (4 + b) * SW_STRIDE;
    const float* wp2 = sw + (8 + b) * SW_STRIDE;

    const float* hin  = g_hA;
    float*       hout = g_hB;

    for (int t = 0; t < TENC; t++) {
        const float* gp = g_GI0 + (size_t)t * NSEQ * G3;
        float gi0r = gp[(size_t)n0 * G3 + jh];
        float gi0z = gp[(size_t)n0 * G3 + jh + 512];
        float gi0n = gp[(size_t)n0 * G3 + jh + 1024];
        float gi1r = gp[(size_t)n1 * G3 + jh];
        float gi1z = gp[(size_t)n1 * G3 + jh + 512];
        float gi1n = gp[(size_t)n1 * G3 + jh + 1024];

        unsigned long long acc[2][3] = {{0ull,0ull,0ull},{0ull,0ull,0ull}};

        float4 preg[8];
        #pragma unroll
        for (int l = 0; l < 8; l++)
            preg[l] = *(const float4*)(hin + (s_nn + 16 * l) * 512 + s_kq * 4);
        #pragma unroll
        for (int l = 0; l < 8; l++)
            *(float4*)(sh0 + (s_nn + 16 * l) * SH_STRIDE + s_kq * 4) = preg[l];
        __syncthreads();

        #pragma unroll
        for (int c = 0; c < 8; c++) {
            const float* shc = (c & 1) ? sh1 : sh0;
            float*       shn = (c & 1) ? sh0 : sh1;
            int k0 = c * 64;
            if (c < 7) {
                #pragma unroll
                for (int l = 0; l < 8; l++)
                    preg[l] = *(const float4*)(hin + (s_nn + 16 * l) * 512 + (k0 + 64) + s_kq * 4);
            }
            #pragma unroll
            for (int kk = 0; kk < 16; kk++) {
                double2 h0 = *(const double2*)(shc + n0 * SH_STRIDE + kk * 4);
                double2 h1 = *(const double2*)(shc + n1 * SH_STRIDE + kk * 4);
                double2 w0 = *(const double2*)(wp0 + k0 + kk * 4);
                double2 w1 = *(const double2*)(wp1 + k0 + kk * 4);
                double2 w2 = *(const double2*)(wp2 + k0 + kk * 4);
                fma2(acc[0][0], h0.x, w0.x); fma2(acc[0][0], h0.y, w0.y);
                fma2(acc[1][0], h1.x, w0.x); fma2(acc[1][0], h1.y, w0.y);
                fma2(acc[0][1], h0.x, w1.x); fma2(acc[0][1], h0.y, w1.y);
                fma2(acc[1][1], h1.x, w1.x); fma2(acc[1][1], h1.y, w1.y);
                fma2(acc[0][2], h0.x, w2.x); fma2(acc[0][2], h0.y, w2.y);
                fma2(acc[1][2], h1.x, w2.x); fma2(acc[1][2], h1.y, w2.y);
            }
            if (c < 7) {
                #pragma unroll
                for (int l = 0; l < 8; l++)
                    *(float4*)(shn + (s_nn + 16 * l) * SH_STRIDE + s_kq * 4) = preg[l];
            }
            __syncthreads();
        }

        {
            float ar = pairsum(acc[0][0]) + bias[0];
            float az = pairsum(acc[0][1]) + bias[1];
            float an = pairsum(acc[0][2]) + bias[2];
            float r = sigmoidf_(gi0r + ar);
            float z = sigmoidf_(gi0z + az);
            float nn = tanhf(gi0n + r * an);
            float hold = hin[n0 * 512 + jh];
            hout[n0 * 512 + jh] = (1.f - z) * nn + z * hold;
        }
        {
            float ar = pairsum(acc[1][0]) + bias[0];
            float az = pairsum(acc[1][1]) + bias[1];
            float an = pairsum(acc[1][2]) + bias[2];
            float r = sigmoidf_(gi1r + ar);
            float z = sigmoidf_(gi1z + az);
            float nn = tanhf(gi1n + r * an);
            float hold = hin[n1 * 512 + jh];
            hout[n1 * 512 + jh] = (1.f - z) * nn + z * hold;
        }

        grid_barrier();
        const float* tmp = hin; hin = hout; hout = (float*)tmp;
    }

    #pragma unroll
    for (int l = 0; l < 48; l++) {
        int idx = tid + 256 * l;
        int q2 = idx >> 9, k = idx & 511;
        if (q2 < 12) {
            int j = jb * 4 + (q2 & 3) + (q2 >> 2) * 512;
            sw[q2 * SW_STRIDE + k] = Whd[(size_t)j * 512 + k];
        } else {
            int q = q2 - 12;
            int j = jb * 4 + (q & 3) + (q >> 2) * 512;
            sw[q2 * SW_STRIDE + k] = Wid[(size_t)j * CIN + k];
        }
    }
    #pragma unroll
    for (int g = 0; g < 3; g++) bias[g] = bhd[jh + 512 * g];
    __syncthreads();

    const float* ip0 = sw + (12 + b) * SW_STRIDE;
    const float* ip1 = sw + (16 + b) * SW_STRIDE;
    const float* ip2 = sw + (20 + b) * SW_STRIDE;

    for (int t = 0; t < TDEC; t++) {
        const float* gp = g_GI1 + (size_t)t * NSEQ * G3;
        float gi0r = gp[(size_t)n0 * G3 + jh];
        float gi0z = gp[(size_t)n0 * G3 + jh + 512];
        float gi0n = gp[(size_t)n0 * G3 + jh + 1024];
        float gi1r = gp[(size_t)n1 * G3 + jh];
        float gi1z = gp[(size_t)n1 * G3 + jh + 512];
        float gi1n = gp[(size_t)n1 * G3 + jh + 1024];

        unsigned long long accH[2][3] = {{0ull,0ull,0ull},{0ull,0ull,0ull}};
        unsigned long long accI[2][3] = {{0ull,0ull,0ull},{0ull,0ull,0ull}};

        float4 preg[8];
        #pragma unroll
        for (int l = 0; l < 8; l++)
            preg[l] = *(const float4*)(hin + (s_nn + 16 * l) * 512 + s_kq * 4);
        #pragma unroll
        for (int l = 0; l < 8; l++)
            *(float4*)(sh0 + (s_nn + 16 * l) * SH_STRIDE + s_kq * 4) = preg[l];
        __syncthreads();

        #pragma unroll
        for (int c = 0; c < 8; c++) {
            const float* shc = (c & 1) ? sh1 : sh0;
            float*       shn = (c & 1) ? sh0 : sh1;
            int k0 = c * 64;
            if (c < 7) {
                #pragma unroll
                for (int l = 0; l < 8; l++)
                    preg[l] = *(const float4*)(hin + (s_nn + 16 * l) * 512 + (k0 + 64) + s_kq * 4);
            }
            #pragma unroll
            for (int kk = 0; kk < 16; kk++) {
                double2 h0 = *(const double2*)(shc + n0 * SH_STRIDE + kk * 4);
                double2 h1 = *(const double2*)(shc + n1 * SH_STRIDE + kk * 4);
                double2 w0 = *(const double2*)(wp0 + k0 + kk * 4);
                double2 w1 = *(const double2*)(wp1 + k0 + kk * 4);
                double2 w2 = *(const double2*)(wp2 + k0 + kk * 4);
                fma2(accH[0][0], h0.x, w0.x); fma2(accH[0][0], h0.y, w0.y);
                fma2(accH[1][0], h1.x, w0.x); fma2(accH[1][0], h1.y, w0.y);
                fma2(accH[0][1], h0.x, w1.x); fma2(accH[0][1], h0.y, w1.y);
                fma2(accH[1][1], h1.x, w1.x); fma2(accH[1][1], h1.y, w1.y);
                fma2(accH[0][2], h0.x, w2.x); fma2(accH[0][2], h0.y, w2.y);
                fma2(accH[1][2], h1.x, w2.x); fma2(accH[1][2], h1.y, w2.y);
                double2 v0 = *(const double2*)(ip0 + k0 + kk * 4);
                double2 v1 = *(const double2*)(ip1 + k0 + kk * 4);
                double2 v2 = *(const double2*)(ip2 + k0 + kk * 4);
                fma2(accI[0][0], h0.x, v0.x); fma2(accI[0][0], h0.y, v0.y);
                fma2(accI[1][0], h1.x, v0.x); fma2(accI[1][0], h1.y, v0.y);
                fma2(accI[0][1], h0.x, v1.x); fma2(accI[0][1], h0.y, v1.y);
                fma2(accI[1][1], h1.x, v1.x); fma2(accI[1][1], h1.y, v1.y);
                fma2(accI[0][2], h0.x, v2.x); fma2(accI[0][2], h0.y, v2.y);
                fma2(accI[1][2], h1.x, v2.x); fma2(accI[1][2], h1.y, v2.y);
            }
            if (c < 7) {
                #pragma unroll
                for (int l = 0; l < 8; l++)
                    *(float4*)(shn + (s_nn + 16 * l) * SH_STRIDE + s_kq * 4) = preg[l];
            }
            __syncthreads();
        }

        {
            float hr = pairsum(accH[0][0]) + bias[0];
            float hz = pairsum(accH[0][1]) + bias[1];
            float hn = pairsum(accH[0][2]) + bias[2];
            float r = sigmoidf_(gi0r + pairsum(accI[0][0]) + hr);
            float z = sigmoidf_(gi0z + pairsum(accI[0][1]) + hz);
            float nn = tanhf(gi0n + pairsum(accI[0][2]) + r * hn);
            float hold = hin[n0 * 512 + jh];
            float hnew = (1.f - z) * nn + z * hold;
            hout[n0 * 512 + jh] = hnew;
            out[((size_t)a * HID + jh) * 96 + 2 * t] = hnew;
        }
        {
            float hr = pairsum(accH[1][0]) + bias[0];
            float hz = pairsum(accH[1][1]) + bias[1];
            float hn = pairsum(accH[1][2]) + bias[2];
            float r = sigmoidf_(gi1r + pairsum(accI[1][0]) + hr);
            float z = sigmoidf_(gi1z + pairsum(accI[1][1]) + hz);
            float nn = tanhf(gi1n + pairsum(accI[1][2]) + r * hn);
            float hold = hin[n1 * 512 + jh];
            float hnew = (1.f - z) * nn + z * hold;
            hout[n1 * 512 + jh] = hnew;
            out[((size_t)a * HID + jh) * 96 + 2 * t + 1] = hnew;
        }

        if (t < TDEC - 1) {
            grid_barrier();
            const float* tmp = hin; hin = hout; hout = (float*)tmp;
        }
    }
}

// ---------------- launch ----------------
extern "C" void kernel_launch(void* const* d_in, const int* in_sizes, int n_in,
                              void* d_out, int out_size) {
    const float* X0  = (const float*)d_in[0];
    const float* X1  = (const float*)d_in[1];
    const float* Wie = (const float*)d_in[3];
    const float* Whe = (const float*)d_in[4];
    const float* bie = (const float*)d_in[5];
    const float* bhe = (const float*)d_in[6];
    const float* Wid = (const float*)d_in[7];
    const float* Whd = (const float*)d_in[8];
    const float* bid = (const float*)d_in[9];
    const float* bhd = (const float*)d_in[10];
    float* out = (float*)d_out;

    const int SMEM_P = (24 * SW_STRIDE + 2 * 128 * SH_STRIDE) * 4;  // 119552 B
    cudaFuncSetAttribute(rnn_persist, cudaFuncAttributeMaxDynamicSharedMemorySize, SMEM_P);
    cudaFuncSetAttribute(gemm_mma, cudaFuncAttributeMaxDynamicSharedMemorySize, GEMM_SMEM);

    __nv_bfloat16 *Ah, *Al, *A1h, *A1l, *Bh, *Bl, *B1h, *B1l;
    cudaGetSymbolAddress((void**)&Ah,  g_Ah);
    cudaGetSymbolAddress((void**)&Al,  g_Al);
    cudaGetSymbolAddress((void**)&A1h, g_A1h);
    cudaGetSymbolAddress((void**)&A1l, g_A1l);
    cudaGetSymbolAddress((void**)&Bh,  g_Bh);
    cudaGetSymbolAddress((void**)&Bl,  g_Bl);
    cudaGetSymbolAddress((void**)&B1h, g_B1h);
    cudaGetSymbolAddress((void**)&B1l, g_B1l);
    float *GI0, *GI1;
    cudaGetSymbolAddress((void**)&GI0, g_GI0);
    cudaGetSymbolAddress((void**)&GI1, g_GI1);

    dim3 tb(32, 8);
    conv_x0<<<dim3(16, 32, 64), tb>>>(X0);
    conv_x1<<<dim3(3, 16, 64), tb>>>(X1);
    conv_w<<<(1536 * 1024 + 255) / 256, 256>>>(Wie, Bh, Bl, 1024, 1024, 0, (long)1536 * 1024);
    conv_w<<<(1536 * 512 + 255) / 256, 256>>>(Wid, B1h, B1l, 512, 1024, 512, (long)1536 * 512);
    zero_h<<<256, 256>>>();

    gemm_mma<<<dim3(12, 256), 256, GEMM_SMEM>>>(Ah, Al, Bh, Bl, bie, GI0, 1024, 0);
    gemm_mma<<<dim3(12, 48), 256, GEMM_SMEM>>>(A1h, A1l, B1h, B1l, bid, GI1, 512, 1);

    rnn_persist<<<128, 256, SMEM_P>>>(Whe, bhe, Whd, Wid, bhd, out);
}

// round 8
// speedup vs baseline: 2.4271x; 1.0168x over previous
#include <cuda_runtime.h>
#include <cuda_bf16.h>
#include <math.h>
#include <stdint.h>

#define HID   512
#define BATCH 64
#define NSEQ  128
#define TENC  256
#define TDEC  48
#define G3    1536   // 3*H
#define CIN   1024   // 2*H

#define SW_STRIDE 520   // persist: weight row stride
#define SH_STRIDE 68    // persist: h row stride

// ---------------- scratch ----------------
__device__ __align__(16) float g_GI0[(size_t)TENC * NSEQ * G3];
__device__ __align__(16) float g_GI1[(size_t)TDEC * NSEQ * G3];
__device__ __align__(16) __nv_bfloat16 g_Ah[(size_t)32768 * 1024];
__device__ __align__(16) __nv_bfloat16 g_Al[(size_t)32768 * 1024];
__device__ __align__(16) __nv_bfloat16 g_A1h[(size_t)6144 * 512];
__device__ __align__(16) __nv_bfloat16 g_A1l[(size_t)6144 * 512];
__device__ __align__(16) __nv_bfloat16 g_Bh[(size_t)1536 * 1024];
__device__ __align__(16) __nv_bfloat16 g_Bl[(size_t)1536 * 1024];
__device__ __align__(16) __nv_bfloat16 g_B1h[(size_t)1536 * 512];
__device__ __align__(16) __nv_bfloat16 g_B1l[(size_t)1536 * 512];
__device__ float g_hA[NSEQ * HID];
__device__ float g_hB[NSEQ * HID];
__device__ unsigned g_bar_count = 0;
__device__ unsigned g_bar_gen   = 0;

// ---------------- fp32x2 helpers (persist kernel) ----------------
__device__ __forceinline__ void fma2(unsigned long long& acc, double a, double b) {
    asm("fma.rn.f32x2 %0, %1, %2, %0;"
        : "+l"(acc)
        : "l"(__double_as_longlong(a)), "l"(__double_as_longlong(b)));
}
__device__ __forceinline__ float pairsum(unsigned long long v) {
    return __uint_as_float((unsigned)v) + __uint_as_float((unsigned)(v >> 32));
}
__device__ __forceinline__ float sigmoidf_(float x) { return 1.f / (1.f + expf(-x)); }

// ---------------- grid barrier (round-2, empirically best) ----------------
__device__ __forceinline__ void grid_barrier() {
    __syncthreads();
    if (threadIdx.x == 0) {
        unsigned g0 = atomicAdd(&g_bar_gen, 0u);
        __threadfence();
        if (atomicAdd(&g_bar_count, 1u) == gridDim.x - 1) {
            g_bar_count = 0;
            __threadfence();
            atomicAdd(&g_bar_gen, 1u);
        } else {
            while (atomicAdd(&g_bar_gen, 0u) == g0) { }
        }
        __threadfence();
    }
    __syncthreads();
}

// ---------------- mma/ldmatrix/cp.async helpers (portable ISA) ----------------
__device__ __forceinline__ uint32_t smem_u32(const void* p) {
    uint32_t a;
    asm("{ .reg .u64 t; cvta.to.shared.u64 t, %1; cvt.u32.u64 %0, t; }" : "=r"(a) : "l"(p));
    return a;
}
__device__ __forceinline__ void ldsm4(uint32_t* r, uint32_t a) {
    asm volatile("ldmatrix.sync.aligned.m8n8.x4.shared.b16 {%0,%1,%2,%3}, [%4];"
                 : "=r"(r[0]), "=r"(r[1]), "=r"(r[2]), "=r"(r[3]) : "r"(a));
}
__device__ __forceinline__ void mma_bf(float* d, const uint32_t* a, uint32_t b0, uint32_t b1) {
    asm volatile("mma.sync.aligned.m16n8k16.row.col.f32.bf16.bf16.f32 "
                 "{%0,%1,%2,%3}, {%4,%5,%6,%7}, {%8,%9}, {%0,%1,%2,%3};"
                 : "+f"(d[0]), "+f"(d[1]), "+f"(d[2]), "+f"(d[3])
                 : "r"(a[0]), "r"(a[1]), "r"(a[2]), "r"(a[3]), "r"(b0), "r"(b1));
}
__device__ __forceinline__ void cpasync16(uint32_t s, const void* g) {
    asm volatile("cp.async.cg.shared.global [%0], [%1], 16;" :: "r"(s), "l"(g));
}
#define CP_COMMIT() asm volatile("cp.async.commit_group;")
#define CP_WAIT(n)  asm volatile("cp.async.wait_group %0;" :: "n"(n))

// ---------------- conversion kernels ----------------
// X0[b][c][t] fp32 -> Ah/Al[m=b*512+t][k=c] bf16 hi/lo (K-major)
__global__ void conv_x0(const float* __restrict__ X0) {
    __shared__ float tile[32][33];
    int t0 = blockIdx.x * 32, c0 = blockIdx.y * 32, b = blockIdx.z;
    int x = threadIdx.x, y = threadIdx.y;
    #pragma unroll
    for (int yy = y; yy < 32; yy += 8)
        tile[yy][x] = X0[((size_t)(b * 1024 + c0 + yy)) * 512 + t0 + x];
    __syncthreads();
    #pragma unroll
    for (int yy = y; yy < 32; yy += 8) {
        float v = tile[x][yy];
        __nv_bfloat16 hv = __float2bfloat16(v);
        __nv_bfloat16 lv = __float2bfloat16(v - __bfloat162float(hv));
        size_t idx = (size_t)(b * 512 + t0 + yy) * 1024 + c0 + x;
        g_Ah[idx] = hv;
        g_Al[idx] = lv;
    }
}

// X1[b][c][t] fp32 (T=96) -> A1h/A1l[m=b*96+t][k=c], K=512
__global__ void conv_x1(const float* __restrict__ X1) {
    __shared__ float tile[32][33];
    int t0 = blockIdx.x * 32, c0 = blockIdx.y * 32, b = blockIdx.z;
    int x = threadIdx.x, y = threadIdx.y;
    #pragma unroll
    for (int yy = y; yy < 32; yy += 8)
        tile[yy][x] = X1[((size_t)(b * 512 + c0 + yy)) * 96 + t0 + x];
    __syncthreads();
    #pragma unroll
    for (int yy = y; yy < 32; yy += 8) {
        float v = tile[x][yy];
        __nv_bfloat16 hv = __float2bfloat16(v);
        __nv_bfloat16 lv = __float2bfloat16(v - __bfloat162float(hv));
        size_t idx = (size_t)(b * 96 + t0 + yy) * 512 + c0 + x;
        g_A1h[idx] = hv;
        g_A1l[idx] = lv;
    }
}

// W[j][Kin] -> outh/outl[j][Kout], reading src[j*Kin + koff + k]
__global__ void conv_w(const float* __restrict__ src, __nv_bfloat16* outh, __nv_bfloat16* outl,
                       int Kout, int Kin, int koff, long total) {
    long i = (long)blockIdx.x * 256 + threadIdx.x;
    if (i >= total) return;
    long j = i / Kout, k = i - j * Kout;
    float v = src[j * Kin + koff + k];
    __nv_bfloat16 hv = __float2bfloat16(v);
    outh[i] = hv;
    outl[i] = __float2bfloat16(v - __bfloat162float(hv));
}

__global__ void zero_h() {
    int i = blockIdx.x * 256 + threadIdx.x;
    if (i < NSEQ * HID) g_hA[i] = 0.f;
}

// ---------------- mma.sync bf16x3 GI GEMM ----------------
// C[128m x 128j] = A·B^T (+bias): Ah·Bh + Ah·Bl + Al·Bh, fp32 accum.
// Pass-ordered mma schedule: 16 independent fragments between accumulator reuse.
#define TILE_B   10240                      // bytes per padded tile
#define STAGE_B  (4 * TILE_B)               // 40960
#define GEMM_SMEM (2 * STAGE_B)             // 81920

__global__ void __launch_bounds__(256) gemm_mma(
    const __nv_bfloat16* __restrict__ Ah, const __nv_bfloat16* __restrict__ Al,
    const __nv_bfloat16* __restrict__ Bh, const __nv_bfloat16* __restrict__ Bl,
    const float* __restrict__ bias, float* __restrict__ outGI, int K, int mode)
{
    extern __shared__ char smem[];
    const uint32_t sb = smem_u32(smem);
    const int tid  = threadIdx.x;
    const int wid  = tid >> 5;
    const int lane = tid & 31;
    const int j0 = blockIdx.x * 128;
    const int m0 = blockIdx.y * 128;
    const int warpM = (wid & 3) * 32;
    const int warpN = (wid >> 2) * 64;

    float acc[2][8][4];
    #pragma unroll
    for (int mt = 0; mt < 2; mt++)
        #pragma unroll
        for (int f = 0; f < 8; f++)
            #pragma unroll
            for (int r = 0; r < 4; r++) acc[mt][f][r] = 0.f;

    const int NC = K >> 5;

    auto load_chunk = [&](int ch, int stage) {
        uint32_t base = sb + stage * STAGE_B;
        int c0 = ch * 32;
        #pragma unroll
        for (int i = 0; i < 2; i++) {
            int idx = tid + 256 * i;
            int r = idx >> 2, s = idx & 3;
            uint32_t soff = (uint32_t)(r * 80 + s * 16);
            size_t ga = (size_t)(m0 + r) * K + c0 + s * 8;
            size_t gb = (size_t)(j0 + r) * K + c0 + s * 8;
            cpasync16(base + 0 * TILE_B + soff, Ah + ga);
            cpasync16(base + 1 * TILE_B + soff, Al + ga);
            cpasync16(base + 2 * TILE_B + soff, Bh + gb);
            cpasync16(base + 3 * TILE_B + soff, Bl + gb);
        }
    };

    load_chunk(0, 0);
    CP_COMMIT();

    for (int ch = 0; ch < NC; ch++) {
        if (ch + 1 < NC) {
            load_chunk(ch + 1, (ch + 1) & 1);
            CP_COMMIT();
            CP_WAIT(1);
        } else {
            CP_WAIT(0);
        }
        __syncthreads();

        uint32_t base = sb + (ch & 1) * STAGE_B;
        #pragma unroll
        for (int k16 = 0; k16 < 2; k16++) {
            uint32_t koff = (uint32_t)(k16 * 32 + (lane >> 4) * 16);
            uint32_t ah[2][4], al[2][4];
            #pragma unroll
            for (int mt = 0; mt < 2; mt++) {
                uint32_t row = (uint32_t)(warpM + mt * 16 + (lane & 15));
                ldsm4(ah[mt], base + 0 * TILE_B + row * 80 + koff);
                ldsm4(al[mt], base + 1 * TILE_B + row * 80 + koff);
            }
            uint32_t bh[4][4], bl[4][4];
            #pragma unroll
            for (int bt = 0; bt < 4; bt++) {
                uint32_t row = (uint32_t)(warpN + bt * 16 + (lane & 15));
                ldsm4(bh[bt], base + 2 * TILE_B + row * 80 + koff);
                ldsm4(bl[bt], base + 3 * TILE_B + row * 80 + koff);
            }
            // pass 1: Ah*Bh — 16 independent fragments
            #pragma unroll
            for (int mt = 0; mt < 2; mt++)
                #pragma unroll
                for (int bt = 0; bt < 4; bt++) {
                    mma_bf(acc[mt][bt * 2 + 0], ah[mt], bh[bt][0], bh[bt][2]);
                    mma_bf(acc[mt][bt * 2 + 1], ah[mt], bh[bt][1], bh[bt][3]);
                }
            // pass 2: Ah*Bl
            #pragma unroll
            for (int mt = 0; mt < 2; mt++)
                #pragma unroll
                for (int bt = 0; bt < 4; bt++) {
                    mma_bf(acc[mt][bt * 2 + 0], ah[mt], bl[bt][0], bl[bt][2]);
                    mma_bf(acc[mt][bt * 2 + 1], ah[mt], bl[bt][1], bl[bt][3]);
                }
            // pass 3: Al*Bh
            #pragma unroll
            for (int mt = 0; mt < 2; mt++)
                #pragma unroll
                for (int bt = 0; bt < 4; bt++) {
                    mma_bf(acc[mt][bt * 2 + 0], al[mt], bh[bt][0], bh[bt][2]);
                    mma_bf(acc[mt][bt * 2 + 1], al[mt], bh[bt][1], bh[bt][3]);
                }
        }
        __syncthreads();
    }

    // epilogue: bias + scatter (float2 stores)
    float2 bias2[8];
    #pragma unroll
    for (int bt = 0; bt < 4; bt++)
        #pragma unroll
        for (int hf = 0; hf < 2; hf++) {
            int j = j0 + warpN + bt * 16 + hf * 8 + (lane & 3) * 2;
            bias2[bt * 2 + hf] = make_float2(bias[j], bias[j + 1]);
        }

    size_t rb[4];
    #pragma unroll
    for (int mt = 0; mt < 2; mt++)
        #pragma unroll
        for (int u = 0; u < 2; u++) {
            int m = m0 + warpM + mt * 16 + u * 8 + (lane >> 2);
            int bb, t0;
            if (mode == 0) { t0 = m & 511; bb = m >> 9; }
            else           { bb = m / 96; t0 = m - bb * 96; }
            int n = ((t0 & 1) << 6) | bb;
            rb[mt * 2 + u] = ((size_t)((t0 >> 1) * NSEQ + n)) * G3;
        }

    #pragma unroll
    for (int mt = 0; mt < 2; mt++)
        #pragma unroll
        for (int bt = 0; bt < 4; bt++)
            #pragma unroll
            for (int hf = 0; hf < 2; hf++) {
                const float* ac = acc[mt][bt * 2 + hf];
                float2 bz = bias2[bt * 2 + hf];
                int jc = j0 + warpN + bt * 16 + hf * 8 + (lane & 3) * 2;
                float2 v0 = make_float2(ac[0] + bz.x, ac[1] + bz.y);
                float2 v1 = make_float2(ac[2] + bz.x, ac[3] + bz.y);
                *(float2*)(outGI + rb[mt * 2 + 0] + jc) = v0;
                *(float2*)(outGI + rb[mt * 2 + 1] + jc) = v1;
            }
}

// ---------------- persistent recurrence kernel (round-2 + register h carry) ----------------
__global__ void __launch_bounds__(256, 1) rnn_persist(
    const float* __restrict__ Whe, const float* __restrict__ bhe,
    const float* __restrict__ Whd, const float* __restrict__ Wid,
    const float* __restrict__ bhd, float* __restrict__ out)
{
    extern __shared__ float sm[];
    float* sw  = sm;                                  // 24 * 520
    float* sh0 = sm + 24 * SW_STRIDE;                 // 128 * 68
    float* sh1 = sh0 + 128 * SH_STRIDE;               // 128 * 68

    int tid = threadIdx.x;
    int jb  = blockIdx.x;
    int a   = tid >> 2;
    int b   = tid & 3;
    int n0  = a, n1 = a + 64;
    int jh  = jb * 4 + b;

    int s_nn = tid >> 4;
    int s_kq = tid & 15;

    #pragma unroll
    for (int l = 0; l < 24; l++) {
        int idx = tid + 256 * l;
        int q = idx >> 9, k = idx & 511;
        int j = jb * 4 + (q & 3) + (q >> 2) * 512;
        sw[q * SW_STRIDE + k] = Whe[(size_t)j * 512 + k];
    }
    float bias[3];
    #pragma unroll
    for (int g = 0; g < 3; g++) bias[g] = bhe[jh + 512 * g];
    __syncthreads();

    const float* wp0 = sw + b * SW_STRIDE;
    const float* wp1 = sw + (4 + b) * SW_STRIDE;
    const float* wp2 = sw + (8 + b) * SW_STRIDE;

    const float* hin  = g_hA;
    float*       hout = g_hB;

    // h[n0][jh], h[n1][jh] owned by this thread across the whole kernel
    float hprev0 = 0.f, hprev1 = 0.f;

    for (int t = 0; t < TENC; t++) {
        const float* gp = g_GI0 + (size_t)t * NSEQ * G3;
        float gi0r = gp[(size_t)n0 * G3 + jh];
        float gi0z = gp[(size_t)n0 * G3 + jh + 512];
        float gi0n = gp[(size_t)n0 * G3 + jh + 1024];
        float gi1r = gp[(size_t)n1 * G3 + jh];
        float gi1z = gp[(size_t)n1 * G3 + jh + 512];
        float gi1n = gp[(size_t)n1 * G3 + jh + 1024];

        unsigned long long acc[2][3] = {{0ull,0ull,0ull},{0ull,0ull,0ull}};

        float4 preg[8];
        #pragma unroll
        for (int l = 0; l < 8; l++)
            preg[l] = *(const float4*)(hin + (s_nn + 16 * l) * 512 + s_kq * 4);
        #pragma unroll
        for (int l = 0; l < 8; l++)
            *(float4*)(sh0 + (s_nn + 16 * l) * SH_STRIDE + s_kq * 4) = preg[l];
        __syncthreads();

        #pragma unroll
        for (int c = 0; c < 8; c++) {
            const float* shc = (c & 1) ? sh1 : sh0;
            float*       shn = (c & 1) ? sh0 : sh1;
            int k0 = c * 64;
            if (c < 7) {
                #pragma unroll
                for (int l = 0; l < 8; l++)
                    preg[l] = *(const float4*)(hin + (s_nn + 16 * l) * 512 + (k0 + 64) + s_kq * 4);
            }
            #pragma unroll
            for (int kk = 0; kk < 16; kk++) {
                double2 h0 = *(const double2*)(shc + n0 * SH_STRIDE + kk * 4);
                double2 h1 = *(const double2*)(shc + n1 * SH_STRIDE + kk * 4);
                double2 w0 = *(const double2*)(wp0 + k0 + kk * 4);
                double2 w1 = *(const double2*)(wp1 + k0 + kk * 4);
                double2 w2 = *(const double2*)(wp2 + k0 + kk * 4);
                fma2(acc[0][0], h0.x, w0.x); fma2(acc[0][0], h0.y, w0.y);
                fma2(acc[1][0], h1.x, w0.x); fma2(acc[1][0], h1.y, w0.y);
                fma2(acc[0][1], h0.x, w1.x); fma2(acc[0][1], h0.y, w1.y);
                fma2(acc[1][1], h1.x, w1.x); fma2(acc[1][1], h1.y, w1.y);
                fma2(acc[0][2], h0.x, w2.x); fma2(acc[0][2], h0.y, w2.y);
                fma2(acc[1][2], h1.x, w2.x); fma2(acc[1][2], h1.y, w2.y);
            }
            if (c < 7) {
                #pragma unroll
                for (int l = 0; l < 8; l++)
                    *(float4*)(shn + (s_nn + 16 * l) * SH_STRIDE + s_kq * 4) = preg[l];
            }
            __syncthreads();
        }

        {
            float ar = pairsum(acc[0][0]) + bias[0];
            float az = pairsum(acc[0][1]) + bias[1];
            float an = pairsum(acc[0][2]) + bias[2];
            float r = sigmoidf_(gi0r + ar);
            float z = sigmoidf_(gi0z + az);
            float nn = tanhf(gi0n + r * an);
            hprev0 = (1.f - z) * nn + z * hprev0;
            hout[n0 * 512 + jh] = hprev0;
        }
        {
            float ar = pairsum(acc[1][0]) + bias[0];
            float az = pairsum(acc[1][1]) + bias[1];
            float an = pairsum(acc[1][2]) + bias[2];
            float r = sigmoidf_(gi1r + ar);
            float z = sigmoidf_(gi1z + az);
            float nn = tanhf(gi1n + r * an);
            hprev1 = (1.f - z) * nn + z * hprev1;
            hout[n1 * 512 + jh] = hprev1;
        }

        grid_barrier();
        const float* tmp = hin; hin = hout; hout = (float*)tmp;
    }

    #pragma unroll
    for (int l = 0; l < 48; l++) {
        int idx = tid + 256 * l;
        int q2 = idx >> 9, k = idx & 511;
        if (q2 < 12) {
            int j = jb * 4 + (q2 & 3) + (q2 >> 2) * 512;
            sw[q2 * SW_STRIDE + k] = Whd[(size_t)j * 512 + k];
        } else {
            int q = q2 - 12;
            int j = jb * 4 + (q & 3) + (q >> 2) * 512;
            sw[q2 * SW_STRIDE + k] = Wid[(size_t)j * CIN + k];
        }
    }
    #pragma unroll
    for (int g = 0; g < 3; g++) bias[g] = bhd[jh + 512 * g];
    __syncthreads();

    const float* ip0 = sw + (12 + b) * SW_STRIDE;
    const float* ip1 = sw + (16 + b) * SW_STRIDE;
    const float* ip2 = sw + (20 + b) * SW_STRIDE;

    for (int t = 0; t < TDEC; t++) {
        const float* gp = g_GI1 + (size_t)t * NSEQ * G3;
        float gi0r = gp[(size_t)n0 * G3 + jh];
        float gi0z = gp[(size_t)n0 * G3 + jh + 512];
        float gi0n = gp[(size_t)n0 * G3 + jh + 1024];
        float gi1r = gp[(size_t)n1 * G3 + jh];
        float gi1z = gp[(size_t)n1 * G3 + jh + 512];
        float gi1n = gp[(size_t)n1 * G3 + jh + 1024];

        unsigned long long accH[2][3] = {{0ull,0ull,0ull},{0ull,0ull,0ull}};
        unsigned long long accI[2][3] = {{0ull,0ull,0ull},{0ull,0ull,0ull}};

        float4 preg[8];
        #pragma unroll
        for (int l = 0; l < 8; l++)
            preg[l] = *(const float4*)(hin + (s_nn + 16 * l) * 512 + s_kq * 4);
        #pragma unroll
        for (int l = 0; l < 8; l++)
            *(float4*)(sh0 + (s_nn + 16 * l) * SH_STRIDE + s_kq * 4) = preg[l];
        __syncthreads();

        #pragma unroll
        for (int c = 0; c < 8; c++) {
            const float* shc = (c & 1) ? sh1 : sh0;
            float*       shn = (c & 1) ? sh0 : sh1;
            int k0 = c * 64;
            if (c < 7) {
                #pragma unroll
                for (int l = 0; l < 8; l++)
                    preg[l] = *(const float4*)(hin + (s_nn + 16 * l) * 512 + (k0 + 64) + s_kq * 4);
            }
            #pragma unroll
            for (int kk = 0; kk < 16; kk++) {
                double2 h0 = *(const double2*)(shc + n0 * SH_STRIDE + kk * 4);
                double2 h1 = *(const double2*)(shc + n1 * SH_STRIDE + kk * 4);
                double2 w0 = *(const double2*)(wp0 + k0 + kk * 4);
                double2 w1 = *(const double2*)(wp1 + k0 + kk * 4);
                double2 w2 = *(const double2*)(wp2 + k0 + kk * 4);
                fma2(accH[0][0], h0.x, w0.x); fma2(accH[0][0], h0.y, w0.y);
                fma2(accH[1][0], h1.x, w0.x); fma2(accH[1][0], h1.y, w0.y);
                fma2(accH[0][1], h0.x, w1.x); fma2(accH[0][1], h0.y, w1.y);
                fma2(accH[1][1], h1.x, w1.x); fma2(accH[1][1], h1.y, w1.y);
                fma2(accH[0][2], h0.x, w2.x); fma2(accH[0][2], h0.y, w2.y);
                fma2(accH[1][2], h1.x, w2.x); fma2(accH[1][2], h1.y, w2.y);
                double2 v0 = *(const double2*)(ip0 + k0 + kk * 4);
                double2 v1 = *(const double2*)(ip1 + k0 + kk * 4);
                double2 v2 = *(const double2*)(ip2 + k0 + kk * 4);
                fma2(accI[0][0], h0.x, v0.x); fma2(accI[0][0], h0.y, v0.y);
                fma2(accI[1][0], h1.x, v0.x); fma2(accI[1][0], h1.y, v0.y);
                fma2(accI[0][1], h0.x, v1.x); fma2(accI[0][1], h0.y, v1.y);
                fma2(accI[1][1], h1.x, v1.x); fma2(accI[1][1], h1.y, v1.y);
                fma2(accI[0][2], h0.x, v2.x); fma2(accI[0][2], h0.y, v2.y);
                fma2(accI[1][2], h1.x, v2.x); fma2(accI[1][2], h1.y, v2.y);
            }
            if (c < 7) {
                #pragma unroll
                for (int l = 0; l < 8; l++)
                    *(float4*)(shn + (s_nn + 16 * l) * SH_STRIDE + s_kq * 4) = preg[l];
            }
            __syncthreads();
        }

        {
            float hr = pairsum(accH[0][0]) + bias[0];
            float hz = pairsum(accH[0][1]) + bias[1];
            float hn = pairsum(accH[0][2]) + bias[2];
            float r = sigmoidf_(gi0r + pairsum(accI[0][0]) + hr);
            float z = sigmoidf_(gi0z + pairsum(accI[0][1]) + hz);
            float nn = tanhf(gi0n + pairsum(accI[0][2]) + r * hn);
            hprev0 = (1.f - z) * nn + z * hprev0;
            hout[n0 * 512 + jh] = hprev0;
            out[((size_t)a * HID + jh) * 96 + 2 * t] = hprev0;
        }
        {
            float hr = pairsum(accH[1][0]) + bias[0];
            float hz = pairsum(accH[1][1]) + bias[1];
            float hn = pairsum(accH[1][2]) + bias[2];
            float r = sigmoidf_(gi1r + pairsum(accI[1][0]) + hr);
            float z = sigmoidf_(gi1z + pairsum(accI[1][1]) + hz);
            float nn = tanhf(gi1n + pairsum(accI[1][2]) + r * hn);
            hprev1 = (1.f - z) * nn + z * hprev1;
            hout[n1 * 512 + jh] = hprev1;
            out[((size_t)a * HID + jh) * 96 + 2 * t + 1] = hprev1;
        }

        if (t < TDEC - 1) {
            grid_barrier();
            const float* tmp = hin; hin = hout; hout = (float*)tmp;
        }
    }
}

// ---------------- launch ----------------
extern "C" void kernel_launch(void* const* d_in, const int* in_sizes, int n_in,
                              void* d_out, int out_size) {
    const float* X0  = (const float*)d_in[0];
    const float* X1  = (const float*)d_in[1];
    const float* Wie = (const float*)d_in[3];
    const float* Whe = (const float*)d_in[4];
    const float* bie = (const float*)d_in[5];
    const float* bhe = (const float*)d_in[6];
    const float* Wid = (const float*)d_in[7];
    const float* Whd = (const float*)d_in[8];
    const float* bid = (const float*)d_in[9];
    const float* bhd = (const float*)d_in[10];
    float* out = (float*)d_out;

    const int SMEM_P = (24 * SW_STRIDE + 2 * 128 * SH_STRIDE) * 4;  // 119552 B
    cudaFuncSetAttribute(rnn_persist, cudaFuncAttributeMaxDynamicSharedMemorySize, SMEM_P);
    cudaFuncSetAttribute(gemm_mma, cudaFuncAttributeMaxDynamicSharedMemorySize, GEMM_SMEM);

    __nv_bfloat16 *Ah, *Al, *A1h, *A1l, *Bh, *Bl, *B1h, *B1l;
    cudaGetSymbolAddress((void**)&Ah,  g_Ah);
    cudaGetSymbolAddress((void**)&Al,  g_Al);
    cudaGetSymbolAddress((void**)&A1h, g_A1h);
    cudaGetSymbolAddress((void**)&A1l, g_A1l);
    cudaGetSymbolAddress((void**)&Bh,  g_Bh);
    cudaGetSymbolAddress((void**)&Bl,  g_Bl);
    cudaGetSymbolAddress((void**)&B1h, g_B1h);
    cudaGetSymbolAddress((void**)&B1l, g_B1l);
    float *GI0, *GI1;
    cudaGetSymbolAddress((void**)&GI0, g_GI0);
    cudaGetSymbolAddress((void**)&GI1, g_GI1);

    dim3 tb(32, 8);
    conv_x0<<<dim3(16, 32, 64), tb>>>(X0);
    conv_x1<<<dim3(3, 16, 64), tb>>>(X1);
    conv_w<<<(1536 * 1024 + 255) / 256, 256>>>(Wie, Bh, Bl, 1024, 1024, 0, (long)1536 * 1024);
    conv_w<<<(1536 * 512 + 255) / 256, 256>>>(Wid, B1h, B1l, 512, 1024, 512, (long)1536 * 512);
    zero_h<<<256, 256>>>();

    gemm_mma<<<dim3(12, 256), 256, GEMM_SMEM>>>(Ah, Al, Bh, Bl, bie, GI0, 1024, 0);
    gemm_mma<<<dim3(12, 48), 256, GEMM_SMEM>>>(A1h, A1l, B1h, B1l, bid, GI1, 512, 1);

    rnn_persist<<<128, 256, SMEM_P>>>(Whe, bhe, Whd, Wid, bhd, out);
}

// round 9
// speedup vs baseline: 2.4714x; 1.0183x over previous
#include <cuda_runtime.h>
#include <cuda_bf16.h>
#include <math.h>
#include <stdint.h>

#define HID   512
#define BATCH 64
#define NSEQ  128
#define TENC  256
#define TDEC  48
#define G3    1536   // 3*H
#define CIN   1024   // 2*H

#define SW_STRIDE 520   // persist: weight row stride
#define SH_STRIDE 68    // persist: h row stride

// ---------------- scratch ----------------
__device__ __align__(16) float g_GI0[(size_t)TENC * NSEQ * G3];
__device__ __align__(16) float g_GI1[(size_t)TDEC * NSEQ * G3];
__device__ __align__(16) __nv_bfloat16 g_Ah[(size_t)32768 * 1024];
__device__ __align__(16) __nv_bfloat16 g_Al[(size_t)32768 * 1024];
__device__ __align__(16) __nv_bfloat16 g_A1h[(size_t)6144 * 512];
__device__ __align__(16) __nv_bfloat16 g_A1l[(size_t)6144 * 512];
__device__ __align__(16) __nv_bfloat16 g_Bh[(size_t)1536 * 1024];
__device__ __align__(16) __nv_bfloat16 g_Bl[(size_t)1536 * 1024];
__device__ __align__(16) __nv_bfloat16 g_B1h[(size_t)1536 * 512];
__device__ __align__(16) __nv_bfloat16 g_B1l[(size_t)1536 * 512];
__device__ float g_hA[NSEQ * HID];
__device__ float g_hB[NSEQ * HID];
__device__ unsigned g_bar_count = 0;
__device__ unsigned g_bar_gen   = 0;

// ---------------- fp32x2 helpers (persist kernel) ----------------
__device__ __forceinline__ void fma2(unsigned long long& acc, double a, double b) {
    asm("fma.rn.f32x2 %0, %1, %2, %0;"
        : "+l"(acc)
        : "l"(__double_as_longlong(a)), "l"(__double_as_longlong(b)));
}
__device__ __forceinline__ float pairsum(unsigned long long v) {
    return __uint_as_float((unsigned)v) + __uint_as_float((unsigned)(v >> 32));
}
__device__ __forceinline__ float sigmoidf_(float x) { return 1.f / (1.f + expf(-x)); }

// ---------------- grid barrier (round-2, empirically best) ----------------
__device__ __forceinline__ void grid_barrier() {
    __syncthreads();
    if (threadIdx.x == 0) {
        unsigned g0 = atomicAdd(&g_bar_gen, 0u);
        __threadfence();
        if (atomicAdd(&g_bar_count, 1u) == gridDim.x - 1) {
            g_bar_count = 0;
            __threadfence();
            atomicAdd(&g_bar_gen, 1u);
        } else {
            while (atomicAdd(&g_bar_gen, 0u) == g0) { }
        }
        __threadfence();
    }
    __syncthreads();
}

// ---------------- mma/ldmatrix/cp.async helpers (portable ISA) ----------------
__device__ __forceinline__ uint32_t smem_u32(const void* p) {
    uint32_t a;
    asm("{ .reg .u64 t; cvta.to.shared.u64 t, %1; cvt.u32.u64 %0, t; }" : "=r"(a) : "l"(p));
    return a;
}
__device__ __forceinline__ void ldsm4(uint32_t* r, uint32_t a) {
    asm volatile("ldmatrix.sync.aligned.m8n8.x4.shared.b16 {%0,%1,%2,%3}, [%4];"
                 : "=r"(r[0]), "=r"(r[1]), "=r"(r[2]), "=r"(r[3]) : "r"(a));
}
__device__ __forceinline__ void mma_bf(float* d, const uint32_t* a, uint32_t b0, uint32_t b1) {
    asm volatile("mma.sync.aligned.m16n8k16.row.col.f32.bf16.bf16.f32 "
                 "{%0,%1,%2,%3}, {%4,%5,%6,%7}, {%8,%9}, {%0,%1,%2,%3};"
                 : "+f"(d[0]), "+f"(d[1]), "+f"(d[2]), "+f"(d[3])
                 : "r"(a[0]), "r"(a[1]), "r"(a[2]), "r"(a[3]), "r"(b0), "r"(b1));
}
__device__ __forceinline__ void cpasync16(uint32_t s, const void* g) {
    asm volatile("cp.async.cg.shared.global [%0], [%1], 16;" :: "r"(s), "l"(g));
}
#define CP_COMMIT() asm volatile("cp.async.commit_group;")
#define CP_WAIT(n)  asm volatile("cp.async.wait_group %0;" :: "n"(n))

// ---------------- conversion kernels ----------------
__global__ void conv_x0(const float* __restrict__ X0) {
    __shared__ float tile[32][33];
    int t0 = blockIdx.x * 32, c0 = blockIdx.y * 32, b = blockIdx.z;
    int x = threadIdx.x, y = threadIdx.y;
    #pragma unroll
    for (int yy = y; yy < 32; yy += 8)
        tile[yy][x] = X0[((size_t)(b * 1024 + c0 + yy)) * 512 + t0 + x];
    __syncthreads();
    #pragma unroll
    for (int yy = y; yy < 32; yy += 8) {
        float v = tile[x][yy];
        __nv_bfloat16 hv = __float2bfloat16(v);
        __nv_bfloat16 lv = __float2bfloat16(v - __bfloat162float(hv));
        size_t idx = (size_t)(b * 512 + t0 + yy) * 1024 + c0 + x;
        g_Ah[idx] = hv;
        g_Al[idx] = lv;
    }
}

__global__ void conv_x1(const float* __restrict__ X1) {
    __shared__ float tile[32][33];
    int t0 = blockIdx.x * 32, c0 = blockIdx.y * 32, b = blockIdx.z;
    int x = threadIdx.x, y = threadIdx.y;
    #pragma unroll
    for (int yy = y; yy < 32; yy += 8)
        tile[yy][x] = X1[((size_t)(b * 512 + c0 + yy)) * 96 + t0 + x];
    __syncthreads();
    #pragma unroll
    for (int yy = y; yy < 32; yy += 8) {
        float v = tile[x][yy];
        __nv_bfloat16 hv = __float2bfloat16(v);
        __nv_bfloat16 lv = __float2bfloat16(v - __bfloat162float(hv));
        size_t idx = (size_t)(b * 96 + t0 + yy) * 512 + c0 + x;
        g_A1h[idx] = hv;
        g_A1l[idx] = lv;
    }
}

__global__ void conv_w(const float* __restrict__ src, __nv_bfloat16* outh, __nv_bfloat16* outl,
                       int Kout, int Kin, int koff, long total) {
    long i = (long)blockIdx.x * 256 + threadIdx.x;
    if (i >= total) return;
    long j = i / Kout, k = i - j * Kout;
    float v = src[j * Kin + koff + k];
    __nv_bfloat16 hv = __float2bfloat16(v);
    outh[i] = hv;
    outl[i] = __float2bfloat16(v - __bfloat162float(hv));
}

__global__ void zero_h() {
    int i = blockIdx.x * 256 + threadIdx.x;
    if (i < NSEQ * HID) g_hA[i] = 0.f;
}

// ---------------- mma.sync bf16x3 GI GEMM (2 CTAs/SM) ----------------
#define TILE_B   10240                      // bytes per padded tile (128 rows x 80B)
#define STAGE_B  (4 * TILE_B)               // 40960
#define GEMM_SMEM (2 * STAGE_B)             // 81920 -> 2 CTAs/SM fits 160KB

__global__ void __launch_bounds__(256, 2) gemm_mma(
    const __nv_bfloat16* __restrict__ Ah, const __nv_bfloat16* __restrict__ Al,
    const __nv_bfloat16* __restrict__ Bh, const __nv_bfloat16* __restrict__ Bl,
    const float* __restrict__ bias, float* __restrict__ outGI, int K, int mode)
{
    extern __shared__ char smem[];
    const uint32_t sb = smem_u32(smem);
    const int tid  = threadIdx.x;
    const int wid  = tid >> 5;
    const int lane = tid & 31;
    const int j0 = blockIdx.x * 128;
    const int m0 = blockIdx.y * 128;
    const int warpM = (wid & 3) * 32;
    const int warpN = (wid >> 2) * 64;

    float acc[2][8][4];
    #pragma unroll
    for (int mt = 0; mt < 2; mt++)
        #pragma unroll
        for (int f = 0; f < 8; f++)
            #pragma unroll
            for (int r = 0; r < 4; r++) acc[mt][f][r] = 0.f;

    const int NC = K >> 5;

    auto load_chunk = [&](int ch, int stage) {
        uint32_t base = sb + stage * STAGE_B;
        int c0 = ch * 32;
        #pragma unroll
        for (int i = 0; i < 2; i++) {
            int idx = tid + 256 * i;
            int r = idx >> 2, s = idx & 3;
            uint32_t soff = (uint32_t)(r * 80 + s * 16);
            size_t ga = (size_t)(m0 + r) * K + c0 + s * 8;
            size_t gb = (size_t)(j0 + r) * K + c0 + s * 8;
            cpasync16(base + 0 * TILE_B + soff, Ah + ga);
            cpasync16(base + 1 * TILE_B + soff, Al + ga);
            cpasync16(base + 2 * TILE_B + soff, Bh + gb);
            cpasync16(base + 3 * TILE_B + soff, Bl + gb);
        }
    };

    load_chunk(0, 0);
    CP_COMMIT();

    for (int ch = 0; ch < NC; ch++) {
        if (ch + 1 < NC) {
            load_chunk(ch + 1, (ch + 1) & 1);
            CP_COMMIT();
            CP_WAIT(1);
        } else {
            CP_WAIT(0);
        }
        __syncthreads();

        uint32_t base = sb + (ch & 1) * STAGE_B;
        #pragma unroll
        for (int k16 = 0; k16 < 2; k16++) {
            uint32_t koff = (uint32_t)(k16 * 32 + (lane >> 4) * 16);
            uint32_t ah[2][4], al[2][4];
            #pragma unroll
            for (int mt = 0; mt < 2; mt++) {
                uint32_t row = (uint32_t)(warpM + mt * 16 + (lane & 15));
                ldsm4(ah[mt], base + 0 * TILE_B + row * 80 + koff);
                ldsm4(al[mt], base + 1 * TILE_B + row * 80 + koff);
            }
            // per-bt B load keeps live registers low (target: 2 CTAs/SM)
            #pragma unroll
            for (int bt = 0; bt < 4; bt++) {
                uint32_t bh[4], bl[4];
                uint32_t row = (uint32_t)(warpN + bt * 16 + (lane & 15));
                ldsm4(bh, base + 2 * TILE_B + row * 80 + koff);
                ldsm4(bl, base + 3 * TILE_B + row * 80 + koff);
                // pass h: 4 independent acc
                mma_bf(acc[0][bt * 2 + 0], ah[0], bh[0], bh[2]);
                mma_bf(acc[0][bt * 2 + 1], ah[0], bh[1], bh[3]);
                mma_bf(acc[1][bt * 2 + 0], ah[1], bh[0], bh[2]);
                mma_bf(acc[1][bt * 2 + 1], ah[1], bh[1], bh[3]);
                // pass l (Ah*Bl)
                mma_bf(acc[0][bt * 2 + 0], ah[0], bl[0], bl[2]);
                mma_bf(acc[0][bt * 2 + 1], ah[0], bl[1], bl[3]);
                mma_bf(acc[1][bt * 2 + 0], ah[1], bl[0], bl[2]);
                mma_bf(acc[1][bt * 2 + 1], ah[1], bl[1], bl[3]);
                // pass l (Al*Bh)
                mma_bf(acc[0][bt * 2 + 0], al[0], bh[0], bh[2]);
                mma_bf(acc[0][bt * 2 + 1], al[0], bh[1], bh[3]);
                mma_bf(acc[1][bt * 2 + 0], al[1], bh[0], bh[2]);
                mma_bf(acc[1][bt * 2 + 1], al[1], bh[1], bh[3]);
            }
        }
        __syncthreads();
    }

    // epilogue: bias + scatter (float2 stores)
    float2 bias2[8];
    #pragma unroll
    for (int bt = 0; bt < 4; bt++)
        #pragma unroll
        for (int hf = 0; hf < 2; hf++) {
            int j = j0 + warpN + bt * 16 + hf * 8 + (lane & 3) * 2;
            bias2[bt * 2 + hf] = make_float2(bias[j], bias[j + 1]);
        }

    size_t rb[4];
    #pragma unroll
    for (int mt = 0; mt < 2; mt++)
        #pragma unroll
        for (int u = 0; u < 2; u++) {
            int m = m0 + warpM + mt * 16 + u * 8 + (lane >> 2);
            int bb, t0;
            if (mode == 0) { t0 = m & 511; bb = m >> 9; }
            else           { bb = m / 96; t0 = m - bb * 96; }
            int n = ((t0 & 1) << 6) | bb;
            rb[mt * 2 + u] = ((size_t)((t0 >> 1) * NSEQ + n)) * G3;
        }

    #pragma unroll
    for (int mt = 0; mt < 2; mt++)
        #pragma unroll
        for (int bt = 0; bt < 4; bt++)
            #pragma unroll
            for (int hf = 0; hf < 2; hf++) {
                const float* ac = acc[mt][bt * 2 + hf];
                float2 bz = bias2[bt * 2 + hf];
                int jc = j0 + warpN + bt * 16 + hf * 8 + (lane & 3) * 2;
                float2 v0 = make_float2(ac[0] + bz.x, ac[1] + bz.y);
                float2 v1 = make_float2(ac[2] + bz.x, ac[3] + bz.y);
                *(float2*)(outGI + rb[mt * 2 + 0] + jc) = v0;
                *(float2*)(outGI + rb[mt * 2 + 1] + jc) = v1;
            }
}

// ---------------- persistent recurrence kernel (round-2 + register h carry) ----------------
__global__ void __launch_bounds__(256, 1) rnn_persist(
    const float* __restrict__ Whe, const float* __restrict__ bhe,
    const float* __restrict__ Whd, const float* __restrict__ Wid,
    const float* __restrict__ bhd, float* __restrict__ out)
{
    extern __shared__ float sm[];
    float* sw  = sm;                                  // 24 * 520
    float* sh0 = sm + 24 * SW_STRIDE;                 // 128 * 68
    float* sh1 = sh0 + 128 * SH_STRIDE;               // 128 * 68

    int tid = threadIdx.x;
    int jb  = blockIdx.x;
    int a   = tid >> 2;
    int b   = tid & 3;
    int n0  = a, n1 = a + 64;
    int jh  = jb * 4 + b;

    int s_nn = tid >> 4;
    int s_kq = tid & 15;

    #pragma unroll
    for (int l = 0; l < 24; l++) {
        int idx = tid + 256 * l;
        int q = idx >> 9, k = idx & 511;
        int j = jb * 4 + (q & 3) + (q >> 2) * 512;
        sw[q * SW_STRIDE + k] = Whe[(size_t)j * 512 + k];
    }
    float bias[3];
    #pragma unroll
    for (int g = 0; g < 3; g++) bias[g] = bhe[jh + 512 * g];
    __syncthreads();

    const float* wp0 = sw + b * SW_STRIDE;
    const float* wp1 = sw + (4 + b) * SW_STRIDE;
    const float* wp2 = sw + (8 + b) * SW_STRIDE;

    const float* hin  = g_hA;
    float*       hout = g_hB;

    float hprev0 = 0.f, hprev1 = 0.f;

    for (int t = 0; t < TENC; t++) {
        const float* gp = g_GI0 + (size_t)t * NSEQ * G3;
        float gi0r = gp[(size_t)n0 * G3 + jh];
        float gi0z = gp[(size_t)n0 * G3 + jh + 512];
        float gi0n = gp[(size_t)n0 * G3 + jh + 1024];
        float gi1r = gp[(size_t)n1 * G3 + jh];
        float gi1z = gp[(size_t)n1 * G3 + jh + 512];
        float gi1n = gp[(size_t)n1 * G3 + jh + 1024];

        unsigned long long acc[2][3] = {{0ull,0ull,0ull},{0ull,0ull,0ull}};

        float4 preg[8];
        #pragma unroll
        for (int l = 0; l < 8; l++)
            preg[l] = *(const float4*)(hin + (s_nn + 16 * l) * 512 + s_kq * 4);
        #pragma unroll
        for (int l = 0; l < 8; l++)
            *(float4*)(sh0 + (s_nn + 16 * l) * SH_STRIDE + s_kq * 4) = preg[l];
        __syncthreads();

        #pragma unroll
        for (int c = 0; c < 8; c++) {
            const float* shc = (c & 1) ? sh1 : sh0;
            float*       shn = (c & 1) ? sh0 : sh1;
            int k0 = c * 64;
            if (c < 7) {
                #pragma unroll
                for (int l = 0; l < 8; l++)
                    preg[l] = *(const float4*)(hin + (s_nn + 16 * l) * 512 + (k0 + 64) + s_kq * 4);
            }
            #pragma unroll
            for (int kk = 0; kk < 16; kk++) {
                double2 h0 = *(const double2*)(shc + n0 * SH_STRIDE + kk * 4);
                double2 h1 = *(const double2*)(shc + n1 * SH_STRIDE + kk * 4);
                double2 w0 = *(const double2*)(wp0 + k0 + kk * 4);
                double2 w1 = *(const double2*)(wp1 + k0 + kk * 4);
                double2 w2 = *(const double2*)(wp2 + k0 + kk * 4);
                fma2(acc[0][0], h0.x, w0.x); fma2(acc[0][0], h0.y, w0.y);
                fma2(acc[1][0], h1.x, w0.x); fma2(acc[1][0], h1.y, w0.y);
                fma2(acc[0][1], h0.x, w1.x); fma2(acc[0][1], h0.y, w1.y);
                fma2(acc[1][1], h1.x, w1.x); fma2(acc[1][1], h1.y, w1.y);
                fma2(acc[0][2], h0.x, w2.x); fma2(acc[0][2], h0.y, w2.y);
                fma2(acc[1][2], h1.x, w2.x); fma2(acc[1][2], h1.y, w2.y);
            }
            if (c < 7) {
                #pragma unroll
                for (int l = 0; l < 8; l++)
                    *(float4*)(shn + (s_nn + 16 * l) * SH_STRIDE + s_kq * 4) = preg[l];
            }
            __syncthreads();
        }

        {
            float ar = pairsum(acc[0][0]) + bias[0];
            float az = pairsum(acc[0][1]) + bias[1];
            float an = pairsum(acc[0][2]) + bias[2];
            float r = sigmoidf_(gi0r + ar);
            float z = sigmoidf_(gi0z + az);
            float nn = tanhf(gi0n + r * an);
            hprev0 = (1.f - z) * nn + z * hprev0;
            hout[n0 * 512 + jh] = hprev0;
        }
        {
            float ar = pairsum(acc[1][0]) + bias[0];
            float az = pairsum(acc[1][1]) + bias[1];
            float an = pairsum(acc[1][2]) + bias[2];
            float r = sigmoidf_(gi1r + ar);
            float z = sigmoidf_(gi1z + az);
            float nn = tanhf(gi1n + r * an);
            hprev1 = (1.f - z) * nn + z * hprev1;
            hout[n1 * 512 + jh] = hprev1;
        }

        grid_barrier();
        const float* tmp = hin; hin = hout; hout = (float*)tmp;
    }

    #pragma unroll
    for (int l = 0; l < 48; l++) {
        int idx = tid + 256 * l;
        int q2 = idx >> 9, k = idx & 511;
        if (q2 < 12) {
            int j = jb * 4 + (q2 & 3) + (q2 >> 2) * 512;
            sw[q2 * SW_STRIDE + k] = Whd[(size_t)j * 512 + k];
        } else {
            int q = q2 - 12;
            int j = jb * 4 + (q & 3) + (q >> 2) * 512;
            sw[q2 * SW_STRIDE + k] = Wid[(size_t)j * CIN + k];
        }
    }
    #pragma unroll
    for (int g = 0; g < 3; g++) bias[g] = bhd[jh + 512 * g];
    __syncthreads();

    const float* ip0 = sw + (12 + b) * SW_STRIDE;
    const float* ip1 = sw + (16 + b) * SW_STRIDE;
    const float* ip2 = sw + (20 + b) * SW_STRIDE;

    for (int t = 0; t < TDEC; t++) {
        const float* gp = g_GI1 + (size_t)t * NSEQ * G3;
        float gi0r = gp[(size_t)n0 * G3 + jh];
        float gi0z = gp[(size_t)n0 * G3 + jh + 512];
        float gi0n = gp[(size_t)n0 * G3 + jh + 1024];
        float gi1r = gp[(size_t)n1 * G3 + jh];
        float gi1z = gp[(size_t)n1 * G3 + jh + 512];
        float gi1n = gp[(size_t)n1 * G3 + jh + 1024];

        unsigned long long accH[2][3] = {{0ull,0ull,0ull},{0ull,0ull,0ull}};
        unsigned long long accI[2][3] = {{0ull,0ull,0ull},{0ull,0ull,0ull}};

        float4 preg[8];
        #pragma unroll
        for (int l = 0; l < 8; l++)
            preg[l] = *(const float4*)(hin + (s_nn + 16 * l) * 512 + s_kq * 4);
        #pragma unroll
        for (int l = 0; l < 8; l++)
            *(float4*)(sh0 + (s_nn + 16 * l) * SH_STRIDE + s_kq * 4) = preg[l];
        __syncthreads();

        #pragma unroll
        for (int c = 0; c < 8; c++) {
            const float* shc = (c & 1) ? sh1 : sh0;
            float*       shn = (c & 1) ? sh0 : sh1;
            int k0 = c * 64;
            if (c < 7) {
                #pragma unroll
                for (int l = 0; l < 8; l++)
                    preg[l] = *(const float4*)(hin + (s_nn + 16 * l) * 512 + (k0 + 64) + s_kq * 4);
            }
            #pragma unroll
            for (int kk = 0; kk < 16; kk++) {
                double2 h0 = *(const double2*)(shc + n0 * SH_STRIDE + kk * 4);
                double2 h1 = *(const double2*)(shc + n1 * SH_STRIDE + kk * 4);
                double2 w0 = *(const double2*)(wp0 + k0 + kk * 4);
                double2 w1 = *(const double2*)(wp1 + k0 + kk * 4);
                double2 w2 = *(const double2*)(wp2 + k0 + kk * 4);
                fma2(accH[0][0], h0.x, w0.x); fma2(accH[0][0], h0.y, w0.y);
                fma2(accH[1][0], h1.x, w0.x); fma2(accH[1][0], h1.y, w0.y);
                fma2(accH[0][1], h0.x, w1.x); fma2(accH[0][1], h0.y, w1.y);
                fma2(accH[1][1], h1.x, w1.x); fma2(accH[1][1], h1.y, w1.y);
                fma2(accH[0][2], h0.x, w2.x); fma2(accH[0][2], h0.y, w2.y);
                fma2(accH[1][2], h1.x, w2.x); fma2(accH[1][2], h1.y, w2.y);
                double2 v0 = *(const double2*)(ip0 + k0 + kk * 4);
                double2 v1 = *(const double2*)(ip1 + k0 + kk * 4);
                double2 v2 = *(const double2*)(ip2 + k0 + kk * 4);
                fma2(accI[0][0], h0.x, v0.x); fma2(accI[0][0], h0.y, v0.y);
                fma2(accI[1][0], h1.x, v0.x); fma2(accI[1][0], h1.y, v0.y);
                fma2(accI[0][1], h0.x, v1.x); fma2(accI[0][1], h0.y, v1.y);
                fma2(accI[1][1], h1.x, v1.x); fma2(accI[1][1], h1.y, v1.y);
                fma2(accI[0][2], h0.x, v2.x); fma2(accI[0][2], h0.y, v2.y);
                fma2(accI[1][2], h1.x, v2.x); fma2(accI[1][2], h1.y, v2.y);
            }
            if (c < 7) {
                #pragma unroll
                for (int l = 0; l < 8; l++)
                    *(float4*)(shn + (s_nn + 16 * l) * SH_STRIDE + s_kq * 4) = preg[l];
            }
            __syncthreads();
        }

        {
            float hr = pairsum(accH[0][0]) + bias[0];
            float hz = pairsum(accH[0][1]) + bias[1];
            float hn = pairsum(accH[0][2]) + bias[2];
            float r = sigmoidf_(gi0r + pairsum(accI[0][0]) + hr);
            float z = sigmoidf_(gi0z + pairsum(accI[0][1]) + hz);
            float nn = tanhf(gi0n + pairsum(accI[0][2]) + r * hn);
            hprev0 = (1.f - z) * nn + z * hprev0;
            hout[n0 * 512 + jh] = hprev0;
            out[((size_t)a * HID + jh) * 96 + 2 * t] = hprev0;
        }
        {
            float hr = pairsum(accH[1][0]) + bias[0];
            float hz = pairsum(accH[1][1]) + bias[1];
            float hn = pairsum(accH[1][2]) + bias[2];
            float r = sigmoidf_(gi1r + pairsum(accI[1][0]) + hr);
            float z = sigmoidf_(gi1z + pairsum(accI[1][1]) + hz);
            float nn = tanhf(gi1n + pairsum(accI[1][2]) + r * hn);
            hprev1 = (1.f - z) * nn + z * hprev1;
            hout[n1 * 512 + jh] = hprev1;
            out[((size_t)a * HID + jh) * 96 + 2 * t + 1] = hprev1;
        }

        if (t < TDEC - 1) {
            grid_barrier();
            const float* tmp = hin; hin = hout; hout = (float*)tmp;
        }
    }
}

// ---------------- launch ----------------
extern "C" void kernel_launch(void* const* d_in, const int* in_sizes, int n_in,
                              void* d_out, int out_size) {
    const float* X0  = (const float*)d_in[0];
    const float* X1  = (const float*)d_in[1];
    const float* Wie = (const float*)d_in[3];
    const float* Whe = (const float*)d_in[4];
    const float* bie = (const float*)d_in[5];
    const float* bhe = (const float*)d_in[6];
    const float* Wid = (const float*)d_in[7];
    const float* Whd = (const float*)d_in[8];
    const float* bid = (const float*)d_in[9];
    const float* bhd = (const float*)d_in[10];
    float* out = (float*)d_out;

    const int SMEM_P = (24 * SW_STRIDE + 2 * 128 * SH_STRIDE) * 4;  // 119552 B
    cudaFuncSetAttribute(rnn_persist, cudaFuncAttributeMaxDynamicSharedMemorySize, SMEM_P);
    cudaFuncSetAttribute(gemm_mma, cudaFuncAttributeMaxDynamicSharedMemorySize, GEMM_SMEM);

    __nv_bfloat16 *Ah, *Al, *A1h, *A1l, *Bh, *Bl, *B1h, *B1l;
    cudaGetSymbolAddress((void**)&Ah,  g_Ah);
    cudaGetSymbolAddress((void**)&Al,  g_Al);
    cudaGetSymbolAddress((void**)&A1h, g_A1h);
    cudaGetSymbolAddress((void**)&A1l, g_A1l);
    cudaGetSymbolAddress((void**)&Bh,  g_Bh);
    cudaGetSymbolAddress((void**)&Bl,  g_Bl);
    cudaGetSymbolAddress((void**)&B1h, g_B1h);
    cudaGetSymbolAddress((void**)&B1l, g_B1l);
    float *GI0, *GI1;
    cudaGetSymbolAddress((void**)&GI0, g_GI0);
    cudaGetSymbolAddress((void**)&GI1, g_GI1);

    dim3 tb(32, 8);
    conv_x0<<<dim3(16, 32, 64), tb>>>(X0);
    conv_x1<<<dim3(3, 16, 64), tb>>>(X1);
    conv_w<<<(1536 * 1024 + 255) / 256, 256>>>(Wie, Bh, Bl, 1024, 1024, 0, (long)1536 * 1024);
    conv_w<<<(1536 * 512 + 255) / 256, 256>>>(Wid, B1h, B1l, 512, 1024, 512, (long)1536 * 512);
    zero_h<<<256, 256>>>();

    gemm_mma<<<dim3(12, 256), 256, GEMM_SMEM>>>(Ah, Al, Bh, Bl, bie, GI0, 1024, 0);
    gemm_mma<<<dim3(12, 48), 256, GEMM_SMEM>>>(A1h, A1l, B1h, B1l, bid, GI1, 512, 1);

    rnn_persist<<<128, 256, SMEM_P>>>(Whe, bhe, Whd, Wid, bhd, out);
}